// round 6
// baseline (speedup 1.0000x reference)
#include <cuda_runtime.h>
#include <math.h>
#include <stdint.h>

// ---------------- problem constants ----------------
#define B_      16
#define HEADS   8
#define G_      64
#define DH      64
#define NSEQ    3131            // 101*31
#define DM      512
#define NH      8
#define L       64
#define DINPROJ 1042            // 2*DM + 2 + 16
#define CONVDIM 514
#define ROWS    1024            // B_*L

#define FINAL_ELEMS (B_*NSEQ*DM)        // 25,649,152
#define INP_ELEMS   (B_*HEADS*G_*DH)    //    524,288

// ---------------- scratch (device globals; no allocs) ----------------
__device__ float g_u[ROWS*DM];
__device__ float g_zx[ROWS*DINPROJ];
__device__ float g_x[ROWS*DM];
__device__ float g_Bv[ROWS];
__device__ float g_Cv[ROWS];
__device__ float g_dtfw[ROWS*NH];
__device__ float g_dtbw[ROWS*NH];
__device__ float g_dcoef[ROWS*NH];
__device__ float g_y[ROWS*DM];
__device__ float g_o[ROWS*DM];
__device__ float g_outp[B_*HEADS*G_*DH];
__device__ float g_M2[B_*DM*DM];        // 16 x 512 x 512

// ---------------- helpers ----------------
__device__ __forceinline__ float softplus_f(float x) {
    return fmaxf(x, 0.f) + log1pf(expf(-fabsf(x)));
}
__device__ __forceinline__ float silu_f(float x) {
    return x / (1.f + expf(-x));
}

// packed fp32x2 helpers (sm_100+ PTX; ptxas never auto-generates FFMA2)
__device__ __forceinline__ unsigned long long pack_dup(float v) {
    unsigned long long r;
    asm("mov.b64 %0, {%1, %1};" : "=l"(r) : "f"(v));
    return r;
}
__device__ __forceinline__ void ffma2(unsigned long long& d,
                                      unsigned long long a,
                                      unsigned long long b) {
    asm("fma.rn.f32x2 %0, %1, %2, %0;" : "+l"(d) : "l"(a), "l"(b));
}
__device__ __forceinline__ float2 unpack2(unsigned long long v) {
    float2 r;
    asm("mov.b64 {%0, %1}, %2;" : "=f"(r.x), "=f"(r.y) : "l"(v));
    return r;
}

// ---------------- kernels ----------------

// u[b,l, h*64+c] = slice_token[b,h,l,c]
__global__ void k_build_u(const float* __restrict__ st) {
    int idx = blockIdx.x * blockDim.x + threadIdx.x;
    if (idx >= ROWS*DM) return;
    int j   = idx & 511;
    int row = idx >> 9;
    int b = row >> 6, l = row & 63;
    int h = j >> 6,  c = j & 63;
    g_u[idx] = st[(((size_t)(b*HEADS + h)*G_ + l)*DH) + c];
}

// Generic NT GEMM: C[m,n] = sum_k A[m*lda+k]*B[n*ldb+k]
// BM=BN=64, BK=16, 256 threads, 4x4 per thread, packed f32x2 inner loop.
// A tile stored duplicated in shared so FFMA2 needs no register packing.
__global__ void k_gemm_nt(const float* __restrict__ A, int lda,
                          const float* __restrict__ Bm, int ldb,
                          float* __restrict__ C, int ldc,
                          int M, int N, int K) {
    __shared__ __align__(16) float As2[16][136];   // k-major, m duplicated (2*64), 136*4=544B rows (16B mult)
    __shared__ __align__(16) float Bs[16][68];     // 68*4=272B rows (16B mult)
    int tid = threadIdx.x;
    int m0 = blockIdx.y * 64, n0 = blockIdx.x * 64;
    int r  = tid >> 2;
    int c4 = (tid & 3) * 4;
    int ty = tid >> 4, tx = tid & 15;
    unsigned long long acc2[4][2] = {};
    for (int kt = 0; kt < K; kt += 16) {
        float4 av = make_float4(0.f,0.f,0.f,0.f);
        if (m0 + r < M) av = *(const float4*)(A + (size_t)(m0 + r)*lda + kt + c4);
        *(unsigned long long*)&As2[c4+0][2*r] = pack_dup(av.x);
        *(unsigned long long*)&As2[c4+1][2*r] = pack_dup(av.y);
        *(unsigned long long*)&As2[c4+2][2*r] = pack_dup(av.z);
        *(unsigned long long*)&As2[c4+3][2*r] = pack_dup(av.w);
        float4 bv = make_float4(0.f,0.f,0.f,0.f);
        if (n0 + r < N) bv = *(const float4*)(Bm + (size_t)(n0 + r)*ldb + kt + c4);
        Bs[c4+0][r]=bv.x; Bs[c4+1][r]=bv.y; Bs[c4+2][r]=bv.z; Bs[c4+3][r]=bv.w;
        __syncthreads();
#pragma unroll
        for (int kk = 0; kk < 16; kk++) {
            ulonglong2 a01 = *(const ulonglong2*)&As2[kk][8*ty];
            ulonglong2 a23 = *(const ulonglong2*)&As2[kk][8*ty + 4];
            ulonglong2 b01 = *(const ulonglong2*)&Bs[kk][4*tx];
            unsigned long long a[4] = {a01.x, a01.y, a23.x, a23.y};
            unsigned long long bb[2] = {b01.x, b01.y};
#pragma unroll
            for (int i = 0; i < 4; i++)
#pragma unroll
                for (int j = 0; j < 2; j++) ffma2(acc2[i][j], a[i], bb[j]);
        }
        __syncthreads();
    }
#pragma unroll
    for (int i = 0; i < 4; i++) {
        int m = m0 + ty*4 + i;
        if (m >= M) continue;
#pragma unroll
        for (int j = 0; j < 2; j++) {
            float2 v = unpack2(acc2[i][j]);
            int n = n0 + tx*4 + 2*j;
            if (n     < N) C[(size_t)m*ldc + n]     = v.x;
            if (n + 1 < N) C[(size_t)m*ldc + n + 1] = v.y;
        }
    }
}

// dt fw/bw: softplus(raw + dt_bias), stored at original l
__global__ void k_dt(const float* __restrict__ dt_bias) {
    int idx = blockIdx.x * blockDim.x + threadIdx.x;
    if (idx >= ROWS*NH) return;
    int h = idx & 7, row = idx >> 3;
    float bsh = dt_bias[h];
    float vf = g_zx[(size_t)row*DINPROJ + 1026 + h] + bsh;
    float vb = g_zx[(size_t)row*DINPROJ + 1034 + h] + bsh;
    g_dtfw[idx] = softplus_f(vf);
    g_dtbw[idx] = softplus_f(vb);
}

// depthwise causal conv (width 3) + silu on xBC channels; split x / Bv / Cv
__global__ void k_conv(const float* __restrict__ conv_w,
                       const float* __restrict__ conv_b) {
    int idx = blockIdx.x * blockDim.x + threadIdx.x;
    if (idx >= ROWS*CONVDIM) return;
    int ch  = idx % CONVDIM;
    int row = idx / CONVDIM;
    int b = row >> 6, l = row & 63;
    float acc = conv_b[ch];
#pragma unroll
    for (int k = 0; k < 3; k++) {
        int lp = l + k - 2;
        if (lp >= 0)
            acc += conv_w[ch*3 + k] * g_zx[(size_t)((b<<6) + lp)*DINPROJ + 512 + ch];
    }
    float s = silu_f(acc);
    if (ch < 512)       g_x[(size_t)row*512 + ch] = s;
    else if (ch == 512) g_Bv[row] = s;
    else                g_Cv[row] = s;
}

// dcoef[row,h] = x[row,:] . fc_D_w[h,:] + D[h]   (8 warps per row)
__global__ void k_dcoef(const float* __restrict__ fcD,
                        const float* __restrict__ Dp) {
    int row  = blockIdx.x;
    int w    = threadIdx.x >> 5;
    int lane = threadIdx.x & 31;
    const float* xr = g_x + (size_t)row*512;
    const float* fr = fcD + (size_t)w*512;
    float s = 0.f;
    for (int k = lane; k < 512; k += 32) s += xr[k]*fr[k];
#pragma unroll
    for (int o = 16; o > 0; o >>= 1) s += __shfl_down_sync(0xffffffffu, s, o);
    if (lane == 0) g_dcoef[row*8 + w] = s + Dp[w];
}

// bidirectional SSM scan, one block per (b,h), 64 threads (d)
__global__ void k_scan(const float* __restrict__ A_log) {
    int h = blockIdx.x, b = blockIdx.y;
    int tid = threadIdx.x;
    __shared__ float s_afw[L], s_bfw[L], s_abw[L], s_bbw[L], s_C[L];
    __shared__ float s_acc[64][65];
    {
        int l = tid;
        int row = (b<<6) + l;
        float Ah  = -expf(A_log[h]);
        float dtf = g_dtfw[row*8 + h];
        float dtb = g_dtbw[row*8 + h];
        float Bl  = g_Bv[row];
        s_afw[l] = expf(dtf*Ah); s_bfw[l] = dtf*Bl;
        s_abw[l] = expf(dtb*Ah); s_bbw[l] = dtb*Bl;
        s_C[l]   = g_Cv[row];
    }
    __syncthreads();
    int d = tid;
    const float* xcol = g_x + (size_t)(b<<6)*512 + h*64 + d;
    float state = 0.f, cprev = 0.f;
    for (int l = 0; l < L; l++) {
        s_acc[d][l] = state * cprev;
        float xv = xcol[(size_t)l*512];
        state = s_afw[l]*state + s_bfw[l]*xv;
        cprev = s_C[l];
    }
    state = 0.f; cprev = 0.f;
    for (int lr = 0; lr < L; lr++) {
        int lo = 63 - lr;
        float xv = xcol[(size_t)lo*512];
        s_acc[d][lo] += state * cprev;
        state = s_abw[lo]*state + s_bbw[lo]*xv;
        cprev = s_C[lo];
    }
    for (int l = 0; l < L; l++) {
        int row = (b<<6) + l;
        float xv = xcol[(size_t)l*512];
        float v  = s_acc[d][l] + xv * g_dcoef[row*8 + h];
        float z  = g_zx[(size_t)row*DINPROJ + h*64 + d];
        v *= silu_f(z);
        g_y[(size_t)row*512 + h*64 + d] = v;
    }
}

// RMS norm (mean over 512) * norm_w, in-place on g_y
__global__ void k_norm(const float* __restrict__ norm_w) {
    int row = blockIdx.x;
    float* yr = g_y + (size_t)row*512;
    int tid = threadIdx.x;                 // 256
    float v0 = yr[tid], v1 = yr[tid + 256];
    float s = v0*v0 + v1*v1;
    __shared__ float red[8];
#pragma unroll
    for (int o = 16; o > 0; o >>= 1) s += __shfl_down_sync(0xffffffffu, s, o);
    if ((tid & 31) == 0) red[tid >> 5] = s;
    __syncthreads();
    if (tid < 32) {
        float t = (tid < 8) ? red[tid] : 0.f;
#pragma unroll
        for (int o = 4; o > 0; o >>= 1) t += __shfl_down_sync(0xffffffffu, t, o);
        if (tid == 0) red[0] = t;
    }
    __syncthreads();
    float scale = rsqrtf(red[0] * (1.f/512.f) + 1e-5f);
    yr[tid]       = v0 * scale * norm_w[tid];
    yr[tid + 256] = v1 * scale * norm_w[tid + 256];
}

// outp[b,h,g,c] = g_o[(b*64+g)*512 + h*64+c]; also writes output segment
__global__ void k_outp(float* __restrict__ out_seg) {
    int idx = blockIdx.x * blockDim.x + threadIdx.x;
    if (idx >= INP_ELEMS) return;
    int c = idx & 63;
    int g = (idx >> 6) & 63;
    int h = (idx >> 12) & 7;
    int b = idx >> 15;
    float v = g_o[(size_t)((b<<6) + g)*512 + h*64 + c];
    g_outp[idx] = v;
    out_seg[idx] = v;
}

// M2[b, h*64+g, d] = sum_c outp[b,h,g,c]*to_out_w[d, h*64+c]
__global__ void k_gemm_m2(const float* __restrict__ to_out_w) {
    int z = blockIdx.z; int b = z >> 3, h = z & 7;
    const float* A  = g_outp + (size_t)z * 4096;                 // 64x64 (g,c)
    const float* Bm = to_out_w + h*64;                           // rows d, ldb 512
    float* C = g_M2 + (size_t)b*262144 + (size_t)h*64*512;       // rows g, ldc 512
    __shared__ float As[16][68];
    __shared__ float Bs[16][68];
    int tid = threadIdx.x;
    int n0 = blockIdx.x * 64;
    int r = tid >> 2, c4 = (tid & 3) * 4;
    int ty = tid >> 4, tx = tid & 15;
    float acc[4][4] = {};
    for (int kt = 0; kt < 64; kt += 16) {
        float4 av = *(const float4*)(A + (size_t)r*64 + kt + c4);
        As[c4+0][r]=av.x; As[c4+1][r]=av.y; As[c4+2][r]=av.z; As[c4+3][r]=av.w;
        float4 bv = *(const float4*)(Bm + (size_t)(n0 + r)*512 + kt + c4);
        Bs[c4+0][r]=bv.x; Bs[c4+1][r]=bv.y; Bs[c4+2][r]=bv.z; Bs[c4+3][r]=bv.w;
        __syncthreads();
#pragma unroll
        for (int kk = 0; kk < 16; kk++) {
            float a[4], bb[4];
#pragma unroll
            for (int i = 0; i < 4; i++) a[i] = As[kk][ty*4 + i];
#pragma unroll
            for (int j = 0; j < 4; j++) bb[j] = Bs[kk][tx*4 + j];
#pragma unroll
            for (int i = 0; i < 4; i++)
#pragma unroll
                for (int j = 0; j < 4; j++) acc[i][j] += a[i]*bb[j];
        }
        __syncthreads();
    }
#pragma unroll
    for (int i = 0; i < 4; i++)
#pragma unroll
        for (int j = 0; j < 4; j++)
            C[(size_t)(ty*4 + i)*512 + n0 + tx*4 + j] = acc[i][j];
}

// final[b,n,d] = sum_k sw[b, k/64, n, k%64] * M2[b,k,d] + bias[d]
// BM=128(n) BN=128(d) BK=16, 256 threads, 8x8 per thread, packed f32x2.
// A tile stored DUPLICATED in shared: As2[k][2*m] == As2[k][2*m+1] == A value.
__global__ void k_gemm_final(const float* __restrict__ sw,
                             const float* __restrict__ bias,
                             float* __restrict__ out) {
    __shared__ __align__(16) float As2[16][264];   // 264*4=1056B rows (16B mult)
    __shared__ __align__(16) float Bs[16][128];
    int b  = blockIdx.z;
    int n0 = blockIdx.y * 128;    // over NSEQ
    int d0 = blockIdx.x * 128;    // over DM
    int tid = threadIdx.x;
    int ty = tid >> 4, tx = tid & 15;
    const float* M2b = g_M2 + (size_t)b * 262144;
    const float* swb = sw + (size_t)b * HEADS * NSEQ * G_;
    unsigned long long acc2[8][4] = {};
    for (int kt = 0; kt < 512; kt += 16) {
        int h  = kt >> 6;
        int ko = kt & 63;
        // A: 128(n) x 16(k) from slice_weights, duplicated along m
        {
            int r  = tid >> 2;
            int c4 = (tid & 3) * 4;
#pragma unroll
            for (int half = 0; half < 2; half++) {
                int rr = r + half*64;
                int n = n0 + rr;
                float4 v = make_float4(0.f,0.f,0.f,0.f);
                if (n < NSEQ)
                    v = *(const float4*)(swb + ((size_t)h*NSEQ + n)*64 + ko + c4);
                *(unsigned long long*)&As2[c4+0][2*rr] = pack_dup(v.x);
                *(unsigned long long*)&As2[c4+1][2*rr] = pack_dup(v.y);
                *(unsigned long long*)&As2[c4+2][2*rr] = pack_dup(v.z);
                *(unsigned long long*)&As2[c4+3][2*rr] = pack_dup(v.w);
            }
        }
        // B: 16(k) x 128(d) from M2
        {
            int rr = tid >> 4;
            int c8 = (tid & 15) * 8;
            const float* p = M2b + (size_t)(kt + rr)*512 + d0 + c8;
            *(float4*)&Bs[rr][c8]     = *(const float4*)p;
            *(float4*)&Bs[rr][c8 + 4] = *(const float4*)(p + 4);
        }
        __syncthreads();
#pragma unroll
        for (int kk = 0; kk < 16; kk++) {
            ulonglong2 a01 = *(const ulonglong2*)&As2[kk][16*ty + 0];
            ulonglong2 a23 = *(const ulonglong2*)&As2[kk][16*ty + 4];
            ulonglong2 a45 = *(const ulonglong2*)&As2[kk][16*ty + 8];
            ulonglong2 a67 = *(const ulonglong2*)&As2[kk][16*ty + 12];
            ulonglong2 b01 = *(const ulonglong2*)&Bs[kk][tx*8];
            ulonglong2 b23 = *(const ulonglong2*)&Bs[kk][tx*8 + 4];
            unsigned long long a[8] = {a01.x, a01.y, a23.x, a23.y,
                                       a45.x, a45.y, a67.x, a67.y};
            unsigned long long bb[4] = {b01.x, b01.y, b23.x, b23.y};
#pragma unroll
            for (int i = 0; i < 8; i++)
#pragma unroll
                for (int j = 0; j < 4; j++) ffma2(acc2[i][j], a[i], bb[j]);
        }
        __syncthreads();
    }
    float bbv[8];
#pragma unroll
    for (int j = 0; j < 8; j++) bbv[j] = bias[d0 + tx*8 + j];
#pragma unroll
    for (int i = 0; i < 8; i++) {
        int n = n0 + ty*8 + i;
        if (n < NSEQ) {
            float* orow = out + ((size_t)b*NSEQ + n)*512 + d0 + tx*8;
#pragma unroll
            for (int j = 0; j < 4; j++) {
                float2 v = unpack2(acc2[i][j]);
                orow[2*j]     = v.x + bbv[2*j];
                orow[2*j + 1] = v.y + bbv[2*j + 1];
            }
        }
    }
}

// ---------------- launch ----------------
extern "C" void kernel_launch(void* const* d_in, const int* in_sizes, int n_in,
                              void* d_out, int out_size) {
    const float* st       = (const float*)d_in[0];   // slice_token
    const float* sw       = (const float*)d_in[1];   // slice_weights
    const float* w_in     = (const float*)d_in[2];
    const float* conv_w   = (const float*)d_in[3];
    const float* conv_b   = (const float*)d_in[4];
    const float* dt_bias  = (const float*)d_in[5];
    const float* A_log    = (const float*)d_in[6];
    const float* Dp       = (const float*)d_in[7];
    const float* fcD      = (const float*)d_in[8];
    const float* norm_w   = (const float*)d_in[9];
    const float* w_out    = (const float*)d_in[10];
    const float* to_out_w = (const float*)d_in[11];
    const float* to_out_b = (const float*)d_in[12];

    float* out      = (float*)d_out;
    float* inp_seg  = out + (size_t)FINAL_ELEMS;
    float* outp_seg = out + (size_t)FINAL_ELEMS + INP_ELEMS;

    float *p_u, *p_zx, *p_y, *p_o;
    cudaGetSymbolAddress((void**)&p_u,  g_u);
    cudaGetSymbolAddress((void**)&p_zx, g_zx);
    cudaGetSymbolAddress((void**)&p_y,  g_y);
    cudaGetSymbolAddress((void**)&p_o,  g_o);

    // 1. gather u
    k_build_u<<<(ROWS*DM + 255)/256, 256>>>(st);
    // 2. in-projection: zx = u @ w_in^T  (1024 x 1042, K=512)
    k_gemm_nt<<<dim3((DINPROJ + 63)/64, ROWS/64), 256>>>(
        p_u, DM, w_in, DM, p_zx, DINPROJ, ROWS, DINPROJ, DM);
    // 3. dt activations
    k_dt<<<(ROWS*NH + 255)/256, 256>>>(dt_bias);
    // 4. conv + silu + split
    k_conv<<<(ROWS*CONVDIM + 255)/256, 256>>>(conv_w, conv_b);
    // 5. dcoef
    k_dcoef<<<ROWS, 256>>>(fcD, Dp);
    // 6. bidirectional scan (+ D-term + silu(z) gate)
    k_scan<<<dim3(HEADS, B_), 64>>>(A_log);
    // 7. RMS norm
    k_norm<<<ROWS, 256>>>(norm_w);
    // 8. out = y @ w_out^T  (1024 x 512, K=512)
    k_gemm_nt<<<dim3(DM/64, ROWS/64), 256>>>(
        p_y, DM, w_out, DM, p_o, DM, ROWS, DM, DM);
    // 9. outp layout + write segment 3
    k_outp<<<(INP_ELEMS + 255)/256, 256>>>(outp_seg);
    // 10. inp passthrough (segment 2)
    cudaMemcpyAsync(inp_seg, st, (size_t)INP_ELEMS * sizeof(float),
                    cudaMemcpyDeviceToDevice);
    // 11. M2 = per-(b,h) outp @ to_out_w_block^T
    k_gemm_m2<<<dim3(8, 1, B_*HEADS), 256>>>(to_out_w);
    // 12. final = SW @ M2 + bias  (16 batched 3131x512x512)
    k_gemm_final<<<dim3(DM/128, (NSEQ + 127)/128, B_), 256>>>(sw, to_out_b, out);
}

// round 9
// speedup vs baseline: 1.9871x; 1.9871x over previous
#include <cuda_runtime.h>
#include <cuda_bf16.h>
#include <math.h>
#include <stdint.h>

// ---------------- problem constants ----------------
#define B_      16
#define HEADS   8
#define G_      64
#define DH      64
#define NSEQ    3131            // 101*31
#define DM      512
#define NH      8
#define L       64
#define DINPROJ 1042            // 2*DM + 2 + 16
#define CONVDIM 514
#define ROWS    1024            // B_*L

#define FINAL_ELEMS (B_*NSEQ*DM)        // 25,649,152
#define INP_ELEMS   (B_*HEADS*G_*DH)    //    524,288
#define SW_ELEMS    (B_*HEADS*NSEQ*G_)  // 25,649,152

// ---------------- scratch (device globals; no allocs) ----------------
__device__ float g_u[ROWS*DM];
__device__ float g_zx[ROWS*DINPROJ];
__device__ float g_x[ROWS*DM];
__device__ float g_Bv[ROWS];
__device__ float g_Cv[ROWS];
__device__ float g_dtfw[ROWS*NH];
__device__ float g_dtbw[ROWS*NH];
__device__ float g_dcoef[ROWS*NH];
__device__ float g_y[ROWS*DM];
__device__ float g_o[ROWS*DM];
__device__ float g_outp[B_*HEADS*G_*DH];

// bf16 hi/lo split operands for the tensor-core GEMM
__device__ __align__(16) __nv_bfloat16 g_swh[SW_ELEMS];
__device__ __align__(16) __nv_bfloat16 g_swl[SW_ELEMS];
__device__ __align__(16) __nv_bfloat16 g_m2h[B_*DM*DM];   // [b][d][k] K-major
__device__ __align__(16) __nv_bfloat16 g_m2l[B_*DM*DM];

// ---------------- small helpers ----------------
__device__ __forceinline__ float softplus_f(float x) {
    return fmaxf(x, 0.f) + log1pf(expf(-fabsf(x)));
}
__device__ __forceinline__ float silu_f(float x) {
    return x / (1.f + expf(-x));
}
__device__ __forceinline__ uint32_t smem_u32(const void* p) {
    uint32_t a;
    asm("{ .reg .u64 t; cvta.to.shared.u64 t, %1; cvt.u32.u64 %0, t; }"
        : "=r"(a) : "l"(p));
    return a;
}
__device__ __forceinline__ void cp_async16(uint32_t dst, const void* src, uint32_t sz) {
    asm volatile("cp.async.ca.shared.global [%0], [%1], 16, %2;"
                 :: "r"(dst), "l"(src), "r"(sz) : "memory");
}
#define CP_COMMIT() asm volatile("cp.async.commit_group;" ::: "memory")

__device__ __forceinline__ void ldmatrix_x4(uint32_t* r, uint32_t addr) {
    asm volatile("ldmatrix.sync.aligned.m8n8.x4.shared.b16 {%0,%1,%2,%3}, [%4];"
                 : "=r"(r[0]), "=r"(r[1]), "=r"(r[2]), "=r"(r[3]) : "r"(addr));
}
__device__ __forceinline__ void mma_bf16(float* c, const uint32_t* a, const uint32_t* b) {
    asm volatile("mma.sync.aligned.m16n8k16.row.col.f32.bf16.bf16.f32 "
                 "{%0,%1,%2,%3}, {%4,%5,%6,%7}, {%8,%9}, {%0,%1,%2,%3};"
                 : "+f"(c[0]), "+f"(c[1]), "+f"(c[2]), "+f"(c[3])
                 : "r"(a[0]), "r"(a[1]), "r"(a[2]), "r"(a[3]),
                   "r"(b[0]), "r"(b[1]));
}

// ---------------- kernels ----------------

// u[b,l, h*64+c] = slice_token[b,h,l,c]
__global__ void k_build_u(const float* __restrict__ st) {
    int idx = blockIdx.x * blockDim.x + threadIdx.x;
    if (idx >= ROWS*DM) return;
    int j   = idx & 511;
    int row = idx >> 9;
    int b = row >> 6, l = row & 63;
    int h = j >> 6,  c = j & 63;
    g_u[idx] = st[(((size_t)(b*HEADS + h)*G_ + l)*DH) + c];
}

// Generic NT GEMM (scalar fp32): C[m,n] = sum_k A[m,k]*B[n,k]
__global__ void k_gemm_nt(const float* __restrict__ A, int lda,
                          const float* __restrict__ Bm, int ldb,
                          float* __restrict__ C, int ldc,
                          int M, int N, int K) {
    __shared__ float As[16][68];
    __shared__ float Bs[16][68];
    int tid = threadIdx.x;
    int m0 = blockIdx.y * 64, n0 = blockIdx.x * 64;
    int r  = tid >> 2;
    int c4 = (tid & 3) * 4;
    int ty = tid >> 4, tx = tid & 15;
    float acc[4][4] = {};
    for (int kt = 0; kt < K; kt += 16) {
        float4 av = make_float4(0.f,0.f,0.f,0.f);
        if (m0 + r < M) av = *(const float4*)(A + (size_t)(m0 + r)*lda + kt + c4);
        As[c4+0][r]=av.x; As[c4+1][r]=av.y; As[c4+2][r]=av.z; As[c4+3][r]=av.w;
        float4 bv = make_float4(0.f,0.f,0.f,0.f);
        if (n0 + r < N) bv = *(const float4*)(Bm + (size_t)(n0 + r)*ldb + kt + c4);
        Bs[c4+0][r]=bv.x; Bs[c4+1][r]=bv.y; Bs[c4+2][r]=bv.z; Bs[c4+3][r]=bv.w;
        __syncthreads();
#pragma unroll
        for (int kk = 0; kk < 16; kk++) {
            float a[4], b[4];
#pragma unroll
            for (int i = 0; i < 4; i++) a[i] = As[kk][ty*4 + i];
#pragma unroll
            for (int j = 0; j < 4; j++) b[j] = Bs[kk][tx*4 + j];
#pragma unroll
            for (int i = 0; i < 4; i++)
#pragma unroll
                for (int j = 0; j < 4; j++) acc[i][j] += a[i]*b[j];
        }
        __syncthreads();
    }
#pragma unroll
    for (int i = 0; i < 4; i++) {
        int m = m0 + ty*4 + i;
        if (m >= M) continue;
#pragma unroll
        for (int j = 0; j < 4; j++) {
            int n = n0 + tx*4 + j;
            if (n >= N) continue;
            C[(size_t)m*ldc + n] = acc[i][j];
        }
    }
}

// dt fw/bw: softplus(raw + dt_bias)
__global__ void k_dt(const float* __restrict__ dt_bias) {
    int idx = blockIdx.x * blockDim.x + threadIdx.x;
    if (idx >= ROWS*NH) return;
    int h = idx & 7, row = idx >> 3;
    float bsh = dt_bias[h];
    float vf = g_zx[(size_t)row*DINPROJ + 1026 + h] + bsh;
    float vb = g_zx[(size_t)row*DINPROJ + 1034 + h] + bsh;
    g_dtfw[idx] = softplus_f(vf);
    g_dtbw[idx] = softplus_f(vb);
}

// depthwise causal conv (width 3) + silu; split x / Bv / Cv
__global__ void k_conv(const float* __restrict__ conv_w,
                       const float* __restrict__ conv_b) {
    int idx = blockIdx.x * blockDim.x + threadIdx.x;
    if (idx >= ROWS*CONVDIM) return;
    int ch  = idx % CONVDIM;
    int row = idx / CONVDIM;
    int b = row >> 6, l = row & 63;
    float acc = conv_b[ch];
#pragma unroll
    for (int k = 0; k < 3; k++) {
        int lp = l + k - 2;
        if (lp >= 0)
            acc += conv_w[ch*3 + k] * g_zx[(size_t)((b<<6) + lp)*DINPROJ + 512 + ch];
    }
    float s = silu_f(acc);
    if (ch < 512)       g_x[(size_t)row*512 + ch] = s;
    else if (ch == 512) g_Bv[row] = s;
    else                g_Cv[row] = s;
}

// dcoef[row,h] = x[row,:] . fc_D_w[h,:] + D[h]
__global__ void k_dcoef(const float* __restrict__ fcD,
                        const float* __restrict__ Dp) {
    int row  = blockIdx.x;
    int w    = threadIdx.x >> 5;
    int lane = threadIdx.x & 31;
    const float* xr = g_x + (size_t)row*512;
    const float* fr = fcD + (size_t)w*512;
    float s = 0.f;
    for (int k = lane; k < 512; k += 32) s += xr[k]*fr[k];
#pragma unroll
    for (int o = 16; o > 0; o >>= 1) s += __shfl_down_sync(0xffffffffu, s, o);
    if (lane == 0) g_dcoef[row*8 + w] = s + Dp[w];
}

// bidirectional SSM scan
__global__ void k_scan(const float* __restrict__ A_log) {
    int h = blockIdx.x, b = blockIdx.y;
    int tid = threadIdx.x;
    __shared__ float s_afw[L], s_bfw[L], s_abw[L], s_bbw[L], s_C[L];
    __shared__ float s_acc[64][65];
    {
        int l = tid;
        int row = (b<<6) + l;
        float Ah  = -expf(A_log[h]);
        float dtf = g_dtfw[row*8 + h];
        float dtb = g_dtbw[row*8 + h];
        float Bl  = g_Bv[row];
        s_afw[l] = expf(dtf*Ah); s_bfw[l] = dtf*Bl;
        s_abw[l] = expf(dtb*Ah); s_bbw[l] = dtb*Bl;
        s_C[l]   = g_Cv[row];
    }
    __syncthreads();
    int d = tid;
    const float* xcol = g_x + (size_t)(b<<6)*512 + h*64 + d;
    float state = 0.f, cprev = 0.f;
    for (int l = 0; l < L; l++) {
        s_acc[d][l] = state * cprev;
        float xv = xcol[(size_t)l*512];
        state = s_afw[l]*state + s_bfw[l]*xv;
        cprev = s_C[l];
    }
    state = 0.f; cprev = 0.f;
    for (int lr = 0; lr < L; lr++) {
        int lo = 63 - lr;
        float xv = xcol[(size_t)lo*512];
        s_acc[d][lo] += state * cprev;
        state = s_abw[lo]*state + s_bbw[lo]*xv;
        cprev = s_C[lo];
    }
    for (int l = 0; l < L; l++) {
        int row = (b<<6) + l;
        float xv = xcol[(size_t)l*512];
        float v  = s_acc[d][l] + xv * g_dcoef[row*8 + h];
        float z  = g_zx[(size_t)row*DINPROJ + h*64 + d];
        v *= silu_f(z);
        g_y[(size_t)row*512 + h*64 + d] = v;
    }
}

// RMS norm * norm_w, in-place on g_y
__global__ void k_norm(const float* __restrict__ norm_w) {
    int row = blockIdx.x;
    float* yr = g_y + (size_t)row*512;
    int tid = threadIdx.x;                 // 256
    float v0 = yr[tid], v1 = yr[tid + 256];
    float s = v0*v0 + v1*v1;
    __shared__ float red[8];
#pragma unroll
    for (int o = 16; o > 0; o >>= 1) s += __shfl_down_sync(0xffffffffu, s, o);
    if ((tid & 31) == 0) red[tid >> 5] = s;
    __syncthreads();
    if (tid < 32) {
        float t = (tid < 8) ? red[tid] : 0.f;
#pragma unroll
        for (int o = 4; o > 0; o >>= 1) t += __shfl_down_sync(0xffffffffu, t, o);
        if (tid == 0) red[0] = t;
    }
    __syncthreads();
    float scale = rsqrtf(red[0] * (1.f/512.f) + 1e-5f);
    yr[tid]       = v0 * scale * norm_w[tid];
    yr[tid + 256] = v1 * scale * norm_w[tid + 256];
}

// outp[b,h,g,c] = g_o[(b*64+g)*512 + h*64+c]; also writes output segment 3
__global__ void k_outp(float* __restrict__ out_seg) {
    int idx = blockIdx.x * blockDim.x + threadIdx.x;
    if (idx >= INP_ELEMS) return;
    int c = idx & 63;
    int g = (idx >> 6) & 63;
    int h = (idx >> 12) & 7;
    int b = idx >> 15;
    float v = g_o[(size_t)((b<<6) + g)*512 + h*64 + c];
    g_outp[idx] = v;
    out_seg[idx] = v;
}

// sw fp32 -> bf16 hi/lo split (vectorized x4)
__global__ void k_cvt_sw(const float* __restrict__ sw) {
    int idx4 = blockIdx.x * blockDim.x + threadIdx.x;
    if (idx4 >= SW_ELEMS/4) return;
    float4 v = *(const float4*)(sw + (size_t)idx4*4);
    __nv_bfloat16 h0 = __float2bfloat16(v.x);
    __nv_bfloat16 h1 = __float2bfloat16(v.y);
    __nv_bfloat16 h2 = __float2bfloat16(v.z);
    __nv_bfloat16 h3 = __float2bfloat16(v.w);
    __nv_bfloat162* ph = (__nv_bfloat162*)(g_swh + (size_t)idx4*4);
    __nv_bfloat162* pl = (__nv_bfloat162*)(g_swl + (size_t)idx4*4);
    ph[0] = __nv_bfloat162(h0, h1);
    ph[1] = __nv_bfloat162(h2, h3);
    pl[0] = __nv_bfloat162(__float2bfloat16(v.x - __bfloat162float(h0)),
                           __float2bfloat16(v.y - __bfloat162float(h1)));
    pl[1] = __nv_bfloat162(__float2bfloat16(v.z - __bfloat162float(h2)),
                           __float2bfloat16(v.w - __bfloat162float(h3)));
}

// M2T[b, d, h*64+g] = sum_c outp[b,h,g,c]*to_out_w[d, h*64+c]
// epilogue stores bf16 hi/lo K-major directly
__global__ void k_gemm_m2(const float* __restrict__ to_out_w) {
    int z = blockIdx.z; int b = z >> 3, h = z & 7;
    const float* A  = g_outp + (size_t)z * 4096;                 // 64x64 (g,c)
    const float* Bm = to_out_w + h*64;                           // rows d, ldb 512
    __shared__ float As[16][68];
    __shared__ float Bs[16][68];
    int tid = threadIdx.x;
    int n0 = blockIdx.x * 64;    // over d
    int r = tid >> 2, c4 = (tid & 3) * 4;
    int ty = tid >> 4, tx = tid & 15;
    float acc[4][4] = {};
    for (int kt = 0; kt < 64; kt += 16) {
        float4 av = *(const float4*)(A + (size_t)r*64 + kt + c4);
        As[c4+0][r]=av.x; As[c4+1][r]=av.y; As[c4+2][r]=av.z; As[c4+3][r]=av.w;
        float4 bv = *(const float4*)(Bm + (size_t)(n0 + r)*512 + kt + c4);
        Bs[c4+0][r]=bv.x; Bs[c4+1][r]=bv.y; Bs[c4+2][r]=bv.z; Bs[c4+3][r]=bv.w;
        __syncthreads();
#pragma unroll
        for (int kk = 0; kk < 16; kk++) {
            float a[4], bb[4];
#pragma unroll
            for (int i = 0; i < 4; i++) a[i] = As[kk][ty*4 + i];
#pragma unroll
            for (int j = 0; j < 4; j++) bb[j] = Bs[kk][tx*4 + j];
#pragma unroll
            for (int i = 0; i < 4; i++)
#pragma unroll
                for (int j = 0; j < 4; j++) acc[i][j] += a[i]*bb[j];
        }
        __syncthreads();
    }
    // transposed store as bf16 hi/lo: row = d, col = k = h*64 + g
#pragma unroll
    for (int i = 0; i < 4; i++)
#pragma unroll
        for (int j = 0; j < 4; j++) {
            float v = acc[i][j];
            __nv_bfloat16 hi = __float2bfloat16(v);
            size_t o = (size_t)b*262144
                     + (size_t)(n0 + tx*4 + j)*512 + (h*64 + ty*4 + i);
            g_m2h[o] = hi;
            g_m2l[o] = __float2bfloat16(v - __bfloat162float(hi));
        }
}

// ================= HMMA bf16-split big GEMM =================
// final[b,n,d] = sum_k sw[b,n,k]*M2T[b,d,k] + bias[d]
// Tile 128(n) x 128(d), BK=32, 8 warps (warp tile 64x32), cp.async 2-stage.
__global__ void __launch_bounds__(256)
k_gemm_final_mma(const float* __restrict__ bias, float* __restrict__ out) {
    extern __shared__ __align__(16) char dsm[];
    // layout per buffer (32KB): Ah 8K | Al 8K | Bh 8K | Bl 8K
    uint32_t sbase = smem_u32(dsm);

    int tid = threadIdx.x;
    int lane = tid & 31, warp = tid >> 5;
    int wm = warp >> 2, wn = warp & 3;          // 2 x 4 warp grid
    int b  = blockIdx.z;
    int d0 = blockIdx.x * 128;
    int n0 = blockIdx.y * 128;

    const size_t swoff = (size_t)b * HEADS * NSEQ * 64;
    const size_t m2off = (size_t)b * 262144;

    float acc[4][4][4] = {};    // [mt][nt][frag]

    // ---- load issue for iteration it into buffer buf ----
#define ISSUE_LOADS(it, buf) do {                                           \
    int kt_ = (it) * 32;                                                    \
    int h_  = kt_ >> 6, k64_ = kt_ & 63;                                    \
    uint32_t base_ = sbase + (buf) * 32768;                                 \
    _Pragma("unroll")                                                       \
    for (int t_ = 0; t_ < 2; t_++) {                                        \
        int chunk_ = tid * 2 + t_;              /* 0..511 */                \
        int row_ = chunk_ >> 2, c_ = chunk_ & 3;                            \
        uint32_t doff_ = (uint32_t)(row_*64 + ((c_ ^ (row_ & 3)) << 4));    \
        int n_ = n0 + row_;                                                 \
        int nc_ = (n_ < NSEQ) ? n_ : (NSEQ - 1);                            \
        uint32_t sz_ = (n_ < NSEQ) ? 16u : 0u;                              \
        size_t aoff_ = swoff + (((size_t)h_*NSEQ + nc_)*64 + k64_ + c_*8);  \
        cp_async16(base_          + doff_, g_swh + aoff_, sz_);             \
        cp_async16(base_ +  8192u + doff_, g_swl + aoff_, sz_);             \
        int d_ = d0 + row_;                                                 \
        size_t boff_ = m2off + ((size_t)d_*512 + kt_ + c_*8);               \
        cp_async16(base_ + 16384u + doff_, g_m2h + boff_, 16u);             \
        cp_async16(base_ + 24576u + doff_, g_m2l + boff_, 16u);             \
    }                                                                       \
    CP_COMMIT();                                                            \
} while (0)

    ISSUE_LOADS(0, 0);
    for (int it = 0; it < 16; it++) {
        int buf = it & 1;
        if (it + 1 < 16) {
            ISSUE_LOADS(it + 1, buf ^ 1);
            asm volatile("cp.async.wait_group 1;" ::: "memory");
        } else {
            asm volatile("cp.async.wait_group 0;" ::: "memory");
        }
        __syncthreads();

        uint32_t Ah = sbase + buf*32768;
        uint32_t Al = Ah + 8192;
        uint32_t Bh = Ah + 16384;
        uint32_t Bl = Ah + 24576;

        int q  = lane >> 3;       // quadrant
        int ri = lane & 7;
#pragma unroll
        for (int kh = 0; kh < 2; kh++) {
            int cbase = 2*kh;
            uint32_t afh[4][4], afl[4][4];
#pragma unroll
            for (int mt = 0; mt < 4; mt++) {
                int row = wm*64 + mt*16 + ((q & 1) << 3) + ri;
                int c   = cbase + (q >> 1);
                uint32_t off = (uint32_t)(row*64 + ((c ^ (row & 3)) << 4));
                ldmatrix_x4(afh[mt], Ah + off);
                ldmatrix_x4(afl[mt], Al + off);
            }
            uint32_t bfh[4][2], bfl[4][2];
#pragma unroll
            for (int pr = 0; pr < 2; pr++) {
                int row = wn*32 + pr*16 + ((q >> 1) << 3) + ri;
                int c   = cbase + (q & 1);
                uint32_t off = (uint32_t)(row*64 + ((c ^ (row & 3)) << 4));
                uint32_t r4[4];
                ldmatrix_x4(r4, Bh + off);
                bfh[pr*2+0][0]=r4[0]; bfh[pr*2+0][1]=r4[1];
                bfh[pr*2+1][0]=r4[2]; bfh[pr*2+1][1]=r4[3];
                ldmatrix_x4(r4, Bl + off);
                bfl[pr*2+0][0]=r4[0]; bfl[pr*2+0][1]=r4[1];
                bfl[pr*2+1][0]=r4[2]; bfl[pr*2+1][1]=r4[3];
            }
#pragma unroll
            for (int mt = 0; mt < 4; mt++)
#pragma unroll
                for (int nt = 0; nt < 4; nt++) {
                    mma_bf16(acc[mt][nt], afh[mt], bfh[nt]);
                    mma_bf16(acc[mt][nt], afh[mt], bfl[nt]);
                    mma_bf16(acc[mt][nt], afl[mt], bfh[nt]);
                }
        }
        __syncthreads();
    }
#undef ISSUE_LOADS

    // ---- epilogue ----
#pragma unroll
    for (int mt = 0; mt < 4; mt++) {
        int rbase = n0 + wm*64 + mt*16 + (lane >> 2);
#pragma unroll
        for (int half = 0; half < 2; half++) {
            int n = rbase + half*8;
            if (n < NSEQ) {
                float* orow = out + ((size_t)b*NSEQ + n)*512;
#pragma unroll
                for (int nt = 0; nt < 4; nt++) {
                    int dcol = d0 + wn*32 + nt*8 + 2*(lane & 3);
                    float2 v;
                    v.x = acc[mt][nt][half*2+0] + bias[dcol];
                    v.y = acc[mt][nt][half*2+1] + bias[dcol+1];
                    *(float2*)(orow + dcol) = v;
                }
            }
        }
    }
}

// ---------------- launch ----------------
extern "C" void kernel_launch(void* const* d_in, const int* in_sizes, int n_in,
                              void* d_out, int out_size) {
    const float* st       = (const float*)d_in[0];   // slice_token
    const float* sw       = (const float*)d_in[1];   // slice_weights
    const float* w_in     = (const float*)d_in[2];
    const float* conv_w   = (const float*)d_in[3];
    const float* conv_b   = (const float*)d_in[4];
    const float* dt_bias  = (const float*)d_in[5];
    const float* A_log    = (const float*)d_in[6];
    const float* Dp       = (const float*)d_in[7];
    const float* fcD      = (const float*)d_in[8];
    const float* norm_w   = (const float*)d_in[9];
    const float* w_out    = (const float*)d_in[10];
    const float* to_out_w = (const float*)d_in[11];
    const float* to_out_b = (const float*)d_in[12];

    float* out      = (float*)d_out;
    float* inp_seg  = out + (size_t)FINAL_ELEMS;
    float* outp_seg = out + (size_t)FINAL_ELEMS + INP_ELEMS;

    float *p_u, *p_zx, *p_y, *p_o;
    cudaGetSymbolAddress((void**)&p_u,  g_u);
    cudaGetSymbolAddress((void**)&p_zx, g_zx);
    cudaGetSymbolAddress((void**)&p_y,  g_y);
    cudaGetSymbolAddress((void**)&p_o,  g_o);

    const int DSMEM = 65536;   // 2 x 32KB buffers
    cudaFuncSetAttribute(k_gemm_final_mma,
                         cudaFuncAttributeMaxDynamicSharedMemorySize, DSMEM);

    // 0. sw -> bf16 hi/lo split (independent; do it first)
    k_cvt_sw<<<(SW_ELEMS/4 + 255)/256, 256>>>(sw);
    // 1. gather u
    k_build_u<<<(ROWS*DM + 255)/256, 256>>>(st);
    // 2. in-projection: zx = u @ w_in^T  (1024 x 1042, K=512)
    k_gemm_nt<<<dim3((DINPROJ + 63)/64, ROWS/64), 256>>>(
        p_u, DM, w_in, DM, p_zx, DINPROJ, ROWS, DINPROJ, DM);
    // 3. dt activations
    k_dt<<<(ROWS*NH + 255)/256, 256>>>(dt_bias);
    // 4. conv + silu + split
    k_conv<<<(ROWS*CONVDIM + 255)/256, 256>>>(conv_w, conv_b);
    // 5. dcoef
    k_dcoef<<<ROWS, 256>>>(fcD, Dp);
    // 6. bidirectional scan (+ D-term + silu(z) gate)
    k_scan<<<dim3(HEADS, B_), 64>>>(A_log);
    // 7. RMS norm
    k_norm<<<ROWS, 256>>>(norm_w);
    // 8. out = y @ w_out^T  (1024 x 512, K=512)
    k_gemm_nt<<<dim3(DM/64, ROWS/64), 256>>>(
        p_y, DM, w_out, DM, p_o, DM, ROWS, DM, DM);
    // 9. outp layout + write segment 3
    k_outp<<<(INP_ELEMS + 255)/256, 256>>>(outp_seg);
    // 10. inp passthrough (segment 2)
    cudaMemcpyAsync(inp_seg, st, (size_t)INP_ELEMS * sizeof(float),
                    cudaMemcpyDeviceToDevice);
    // 11. M2T = per-(b,h) outp @ to_out_w_block^T -> bf16 hi/lo K-major
    k_gemm_m2<<<dim3(8, 1, B_*HEADS), 256>>>(to_out_w);
    // 12. final = SW @ M2 + bias via HMMA bf16-split (16 x 3131x512x512)
    k_gemm_final_mma<<<dim3(DM/128, (NSEQ + 127)/128, B_), 256, DSMEM>>>(
        to_out_b, out);
}

// round 10
// speedup vs baseline: 2.6890x; 1.3532x over previous
#include <cuda_runtime.h>
#include <cuda_bf16.h>
#include <math.h>
#include <stdint.h>

// ---------------- problem constants ----------------
#define B_      16
#define HEADS   8
#define G_      64
#define DH      64
#define NSEQ    3131            // 101*31
#define DM      512
#define NH      8
#define L       64
#define DINPROJ 1042            // 2*DM + 2 + 16
#define CONVDIM 514
#define ROWS    1024            // B_*L

#define FINAL_ELEMS (B_*NSEQ*DM)        // 25,649,152
#define INP_ELEMS   (B_*HEADS*G_*DH)    //    524,288
#define SW_ELEMS    (B_*HEADS*NSEQ*G_)  // 25,649,152

// ---------------- scratch (device globals; no allocs) ----------------
__device__ float g_u[ROWS*DM];
__device__ float g_zx[ROWS*DINPROJ];
__device__ float g_x[ROWS*DM];
__device__ float g_Bv[ROWS];
__device__ float g_Cv[ROWS];
__device__ float g_dtfw[ROWS*NH];
__device__ float g_dtbw[ROWS*NH];
__device__ float g_dcoef[ROWS*NH];
__device__ float g_y[ROWS*DM];
__device__ float g_o[ROWS*DM];
__device__ float g_outp[B_*HEADS*G_*DH];

// tf32-rounded operands for the tensor-core GEMM
__device__ __align__(16) float g_swt[SW_ELEMS];    // sw rounded to tf32
__device__ __align__(16) float g_m2t[B_*DM*DM];    // [b][d][k] K-major, tf32-rounded

// ---------------- small helpers ----------------
__device__ __forceinline__ float softplus_f(float x) {
    return fmaxf(x, 0.f) + log1pf(expf(-fabsf(x)));
}
__device__ __forceinline__ float silu_f(float x) {
    return x / (1.f + expf(-x));
}
__device__ __forceinline__ uint32_t smem_u32(const void* p) {
    uint32_t a;
    asm("{ .reg .u64 t; cvta.to.shared.u64 t, %1; cvt.u32.u64 %0, t; }"
        : "=r"(a) : "l"(p));
    return a;
}
__device__ __forceinline__ float tf32_rna(float x) {
    uint32_t t;
    asm("cvt.rna.tf32.f32 %0, %1;" : "=r"(t) : "f"(x));
    return __uint_as_float(t);
}
__device__ __forceinline__ void cp_async16(uint32_t dst, const void* src, uint32_t sz) {
    asm volatile("cp.async.ca.shared.global [%0], [%1], 16, %2;"
                 :: "r"(dst), "l"(src), "r"(sz) : "memory");
}
#define CP_COMMIT() asm volatile("cp.async.commit_group;" ::: "memory")

__device__ __forceinline__ void mma_tf32(float* c, const uint32_t* a, const uint32_t* b) {
    asm volatile("mma.sync.aligned.m16n8k8.row.col.f32.tf32.tf32.f32 "
                 "{%0,%1,%2,%3}, {%4,%5,%6,%7}, {%8,%9}, {%0,%1,%2,%3};"
                 : "+f"(c[0]), "+f"(c[1]), "+f"(c[2]), "+f"(c[3])
                 : "r"(a[0]), "r"(a[1]), "r"(a[2]), "r"(a[3]),
                   "r"(b[0]), "r"(b[1]));
}

// ---------------- kernels ----------------

// u[b,l, h*64+c] = slice_token[b,h,l,c]
__global__ void k_build_u(const float* __restrict__ st) {
    int idx = blockIdx.x * blockDim.x + threadIdx.x;
    if (idx >= ROWS*DM) return;
    int j   = idx & 511;
    int row = idx >> 9;
    int b = row >> 6, l = row & 63;
    int h = j >> 6,  c = j & 63;
    g_u[idx] = st[(((size_t)(b*HEADS + h)*G_ + l)*DH) + c];
}

// Generic NT GEMM (scalar fp32): C[m,n] = sum_k A[m,k]*B[n,k]
__global__ void k_gemm_nt(const float* __restrict__ A, int lda,
                          const float* __restrict__ Bm, int ldb,
                          float* __restrict__ C, int ldc,
                          int M, int N, int K) {
    __shared__ float As[16][68];
    __shared__ float Bs[16][68];
    int tid = threadIdx.x;
    int m0 = blockIdx.y * 64, n0 = blockIdx.x * 64;
    int r  = tid >> 2;
    int c4 = (tid & 3) * 4;
    int ty = tid >> 4, tx = tid & 15;
    float acc[4][4] = {};
    for (int kt = 0; kt < K; kt += 16) {
        float4 av = make_float4(0.f,0.f,0.f,0.f);
        if (m0 + r < M) av = *(const float4*)(A + (size_t)(m0 + r)*lda + kt + c4);
        As[c4+0][r]=av.x; As[c4+1][r]=av.y; As[c4+2][r]=av.z; As[c4+3][r]=av.w;
        float4 bv = make_float4(0.f,0.f,0.f,0.f);
        if (n0 + r < N) bv = *(const float4*)(Bm + (size_t)(n0 + r)*ldb + kt + c4);
        Bs[c4+0][r]=bv.x; Bs[c4+1][r]=bv.y; Bs[c4+2][r]=bv.z; Bs[c4+3][r]=bv.w;
        __syncthreads();
#pragma unroll
        for (int kk = 0; kk < 16; kk++) {
            float a[4], b[4];
#pragma unroll
            for (int i = 0; i < 4; i++) a[i] = As[kk][ty*4 + i];
#pragma unroll
            for (int j = 0; j < 4; j++) b[j] = Bs[kk][tx*4 + j];
#pragma unroll
            for (int i = 0; i < 4; i++)
#pragma unroll
                for (int j = 0; j < 4; j++) acc[i][j] += a[i]*b[j];
        }
        __syncthreads();
    }
#pragma unroll
    for (int i = 0; i < 4; i++) {
        int m = m0 + ty*4 + i;
        if (m >= M) continue;
#pragma unroll
        for (int j = 0; j < 4; j++) {
            int n = n0 + tx*4 + j;
            if (n >= N) continue;
            C[(size_t)m*ldc + n] = acc[i][j];
        }
    }
}

// dt fw/bw: softplus(raw + dt_bias)
__global__ void k_dt(const float* __restrict__ dt_bias) {
    int idx = blockIdx.x * blockDim.x + threadIdx.x;
    if (idx >= ROWS*NH) return;
    int h = idx & 7, row = idx >> 3;
    float bsh = dt_bias[h];
    float vf = g_zx[(size_t)row*DINPROJ + 1026 + h] + bsh;
    float vb = g_zx[(size_t)row*DINPROJ + 1034 + h] + bsh;
    g_dtfw[idx] = softplus_f(vf);
    g_dtbw[idx] = softplus_f(vb);
}

// depthwise causal conv (width 3) + silu; split x / Bv / Cv
__global__ void k_conv(const float* __restrict__ conv_w,
                       const float* __restrict__ conv_b) {
    int idx = blockIdx.x * blockDim.x + threadIdx.x;
    if (idx >= ROWS*CONVDIM) return;
    int ch  = idx % CONVDIM;
    int row = idx / CONVDIM;
    int b = row >> 6, l = row & 63;
    float acc = conv_b[ch];
#pragma unroll
    for (int k = 0; k < 3; k++) {
        int lp = l + k - 2;
        if (lp >= 0)
            acc += conv_w[ch*3 + k] * g_zx[(size_t)((b<<6) + lp)*DINPROJ + 512 + ch];
    }
    float s = silu_f(acc);
    if (ch < 512)       g_x[(size_t)row*512 + ch] = s;
    else if (ch == 512) g_Bv[row] = s;
    else                g_Cv[row] = s;
}

// dcoef[row,h] = x[row,:] . fc_D_w[h,:] + D[h]
__global__ void k_dcoef(const float* __restrict__ fcD,
                        const float* __restrict__ Dp) {
    int row  = blockIdx.x;
    int w    = threadIdx.x >> 5;
    int lane = threadIdx.x & 31;
    const float* xr = g_x + (size_t)row*512;
    const float* fr = fcD + (size_t)w*512;
    float s = 0.f;
    for (int k = lane; k < 512; k += 32) s += xr[k]*fr[k];
#pragma unroll
    for (int o = 16; o > 0; o >>= 1) s += __shfl_down_sync(0xffffffffu, s, o);
    if (lane == 0) g_dcoef[row*8 + w] = s + Dp[w];
}

// bidirectional SSM scan
__global__ void k_scan(const float* __restrict__ A_log) {
    int h = blockIdx.x, b = blockIdx.y;
    int tid = threadIdx.x;
    __shared__ float s_afw[L], s_bfw[L], s_abw[L], s_bbw[L], s_C[L];
    __shared__ float s_acc[64][65];
    {
        int l = tid;
        int row = (b<<6) + l;
        float Ah  = -expf(A_log[h]);
        float dtf = g_dtfw[row*8 + h];
        float dtb = g_dtbw[row*8 + h];
        float Bl  = g_Bv[row];
        s_afw[l] = expf(dtf*Ah); s_bfw[l] = dtf*Bl;
        s_abw[l] = expf(dtb*Ah); s_bbw[l] = dtb*Bl;
        s_C[l]   = g_Cv[row];
    }
    __syncthreads();
    int d = tid;
    const float* xcol = g_x + (size_t)(b<<6)*512 + h*64 + d;
    float state = 0.f, cprev = 0.f;
    for (int l = 0; l < L; l++) {
        s_acc[d][l] = state * cprev;
        float xv = xcol[(size_t)l*512];
        state = s_afw[l]*state + s_bfw[l]*xv;
        cprev = s_C[l];
    }
    state = 0.f; cprev = 0.f;
    for (int lr = 0; lr < L; lr++) {
        int lo = 63 - lr;
        float xv = xcol[(size_t)lo*512];
        s_acc[d][lo] += state * cprev;
        state = s_abw[lo]*state + s_bbw[lo]*xv;
        cprev = s_C[lo];
    }
    for (int l = 0; l < L; l++) {
        int row = (b<<6) + l;
        float xv = xcol[(size_t)l*512];
        float v  = s_acc[d][l] + xv * g_dcoef[row*8 + h];
        float z  = g_zx[(size_t)row*DINPROJ + h*64 + d];
        v *= silu_f(z);
        g_y[(size_t)row*512 + h*64 + d] = v;
    }
}

// RMS norm * norm_w, in-place on g_y
__global__ void k_norm(const float* __restrict__ norm_w) {
    int row = blockIdx.x;
    float* yr = g_y + (size_t)row*512;
    int tid = threadIdx.x;                 // 256
    float v0 = yr[tid], v1 = yr[tid + 256];
    float s = v0*v0 + v1*v1;
    __shared__ float red[8];
#pragma unroll
    for (int o = 16; o > 0; o >>= 1) s += __shfl_down_sync(0xffffffffu, s, o);
    if ((tid & 31) == 0) red[tid >> 5] = s;
    __syncthreads();
    if (tid < 32) {
        float t = (tid < 8) ? red[tid] : 0.f;
#pragma unroll
        for (int o = 4; o > 0; o >>= 1) t += __shfl_down_sync(0xffffffffu, t, o);
        if (tid == 0) red[0] = t;
    }
    __syncthreads();
    float scale = rsqrtf(red[0] * (1.f/512.f) + 1e-5f);
    yr[tid]       = v0 * scale * norm_w[tid];
    yr[tid + 256] = v1 * scale * norm_w[tid + 256];
}

// outp[b,h,g,c] = g_o[(b*64+g)*512 + h*64+c]; also writes output segment 3
__global__ void k_outp(float* __restrict__ out_seg) {
    int idx = blockIdx.x * blockDim.x + threadIdx.x;
    if (idx >= INP_ELEMS) return;
    int c = idx & 63;
    int g = (idx >> 6) & 63;
    int h = (idx >> 12) & 7;
    int b = idx >> 15;
    float v = g_o[(size_t)((b<<6) + g)*512 + h*64 + c];
    g_outp[idx] = v;
    out_seg[idx] = v;
}

// sw fp32 -> tf32-rounded fp32 (vectorized x4)
__global__ void k_round_sw(const float* __restrict__ sw) {
    int idx4 = blockIdx.x * blockDim.x + threadIdx.x;
    if (idx4 >= SW_ELEMS/4) return;
    float4 v = *(const float4*)(sw + (size_t)idx4*4);
    v.x = tf32_rna(v.x);
    v.y = tf32_rna(v.y);
    v.z = tf32_rna(v.z);
    v.w = tf32_rna(v.w);
    *(float4*)(g_swt + (size_t)idx4*4) = v;
}

// M2T[b, d, h*64+g] = sum_c outp[b,h,g,c]*to_out_w[d, h*64+c]
// epilogue stores tf32-rounded fp32 K-major
__global__ void k_gemm_m2(const float* __restrict__ to_out_w) {
    int z = blockIdx.z; int b = z >> 3, h = z & 7;
    const float* A  = g_outp + (size_t)z * 4096;                 // 64x64 (g,c)
    const float* Bm = to_out_w + h*64;                           // rows d, ldb 512
    __shared__ float As[16][68];
    __shared__ float Bs[16][68];
    int tid = threadIdx.x;
    int n0 = blockIdx.x * 64;    // over d
    int r = tid >> 2, c4 = (tid & 3) * 4;
    int ty = tid >> 4, tx = tid & 15;
    float acc[4][4] = {};
    for (int kt = 0; kt < 64; kt += 16) {
        float4 av = *(const float4*)(A + (size_t)r*64 + kt + c4);
        As[c4+0][r]=av.x; As[c4+1][r]=av.y; As[c4+2][r]=av.z; As[c4+3][r]=av.w;
        float4 bv = *(const float4*)(Bm + (size_t)(n0 + r)*512 + kt + c4);
        Bs[c4+0][r]=bv.x; Bs[c4+1][r]=bv.y; Bs[c4+2][r]=bv.z; Bs[c4+3][r]=bv.w;
        __syncthreads();
#pragma unroll
        for (int kk = 0; kk < 16; kk++) {
            float a[4], bb[4];
#pragma unroll
            for (int i = 0; i < 4; i++) a[i] = As[kk][ty*4 + i];
#pragma unroll
            for (int j = 0; j < 4; j++) bb[j] = Bs[kk][tx*4 + j];
#pragma unroll
            for (int i = 0; i < 4; i++)
#pragma unroll
                for (int j = 0; j < 4; j++) acc[i][j] += a[i]*bb[j];
        }
        __syncthreads();
    }
    // transposed store (row = d, col = k = h*64 + g), tf32-rounded
#pragma unroll
    for (int i = 0; i < 4; i++)
#pragma unroll
        for (int j = 0; j < 4; j++) {
            size_t o = (size_t)b*262144
                     + (size_t)(n0 + tx*4 + j)*512 + (h*64 + ty*4 + i);
            g_m2t[o] = tf32_rna(acc[i][j]);
        }
}

// ================= TF32 MMA big GEMM =================
// final[b,n,d] = sum_k sw[b,n,k]*M2T[b,d,k] + bias[d]
// Tile 128(n) x 128(d), BK=32, 8 warps (warp tile 64x32), cp.async 2-stage.
// smem: fp32 tiles, row stride 36 floats (conflict-free scalar LDS fragments).
#define STG_A_BYTES 18432          // 128 rows * 144 B
#define STG_BYTES   36864          // A + B
__global__ void __launch_bounds__(256)
k_gemm_final_mma(const float* __restrict__ bias, float* __restrict__ out) {
    extern __shared__ __align__(16) char dsm[];
    uint32_t sbase = smem_u32(dsm);

    int tid = threadIdx.x;
    int lane = tid & 31, warp = tid >> 5;
    int wm = warp >> 2, wn = warp & 3;          // 2 x 4 warp grid
    int b  = blockIdx.z;
    int d0 = blockIdx.x * 128;
    int n0 = blockIdx.y * 128;

    const size_t swoff = (size_t)b * HEADS * NSEQ * 64;
    const size_t m2off = (size_t)b * 262144;

    float acc[4][4][4] = {};    // [mt][nt][frag]

#define ISSUE_LOADS(it, buf) do {                                           \
    int kt_ = (it) * 32;                                                    \
    int h_  = kt_ >> 6, k64_ = kt_ & 63;                                    \
    uint32_t base_ = sbase + (buf) * STG_BYTES;                             \
    _Pragma("unroll")                                                       \
    for (int i_ = 0; i_ < 4; i_++) {                                        \
        int id_  = tid + 256 * i_;            /* 0..1023 */                 \
        int row_ = id_ >> 3, c_ = id_ & 7;                                  \
        uint32_t doff_ = (uint32_t)(row_ * 144 + c_ * 16);                  \
        int n_ = n0 + row_;                                                 \
        int nc_ = (n_ < NSEQ) ? n_ : (NSEQ - 1);                            \
        uint32_t sz_ = (n_ < NSEQ) ? 16u : 0u;                              \
        size_t aoff_ = swoff + (((size_t)h_*NSEQ + nc_)*64 + k64_ + c_*4);  \
        cp_async16(base_ + doff_, g_swt + aoff_, sz_);                      \
        int d_ = d0 + row_;                                                 \
        size_t boff_ = m2off + ((size_t)d_*512 + kt_ + c_*4);               \
        cp_async16(base_ + STG_A_BYTES + doff_, g_m2t + boff_, 16u);        \
    }                                                                       \
    CP_COMMIT();                                                            \
} while (0)

    int r4  = lane >> 2;
    int c4l = lane & 3;

    ISSUE_LOADS(0, 0);
    for (int it = 0; it < 16; it++) {
        int buf = it & 1;
        if (it + 1 < 16) {
            ISSUE_LOADS(it + 1, buf ^ 1);
            asm volatile("cp.async.wait_group 1;" ::: "memory");
        } else {
            asm volatile("cp.async.wait_group 0;" ::: "memory");
        }
        __syncthreads();

        const float* As = (const float*)(dsm + buf * STG_BYTES);
        const float* Bs = (const float*)(dsm + buf * STG_BYTES + STG_A_BYTES);

#pragma unroll
        for (int ks = 0; ks < 4; ks++) {
            int col = ks * 8 + c4l;
            uint32_t af[4][4];
#pragma unroll
            for (int mt = 0; mt < 4; mt++) {
                int row = wm*64 + mt*16 + r4;
                af[mt][0] = __float_as_uint(As[row*36 + col]);
                af[mt][1] = __float_as_uint(As[(row+8)*36 + col]);
                af[mt][2] = __float_as_uint(As[row*36 + col + 4]);
                af[mt][3] = __float_as_uint(As[(row+8)*36 + col + 4]);
            }
            uint32_t bf[4][2];
#pragma unroll
            for (int nt = 0; nt < 4; nt++) {
                int n = wn*32 + nt*8 + r4;
                bf[nt][0] = __float_as_uint(Bs[n*36 + col]);
                bf[nt][1] = __float_as_uint(Bs[n*36 + col + 4]);
            }
#pragma unroll
            for (int mt = 0; mt < 4; mt++)
#pragma unroll
                for (int nt = 0; nt < 4; nt++)
                    mma_tf32(acc[mt][nt], af[mt], bf[nt]);
        }
        __syncthreads();
    }
#undef ISSUE_LOADS

    // ---- epilogue ----
#pragma unroll
    for (int mt = 0; mt < 4; mt++) {
        int rbase = n0 + wm*64 + mt*16 + r4;
#pragma unroll
        for (int half = 0; half < 2; half++) {
            int n = rbase + half*8;
            if (n < NSEQ) {
                float* orow = out + ((size_t)b*NSEQ + n)*512;
#pragma unroll
                for (int nt = 0; nt < 4; nt++) {
                    int dcol = d0 + wn*32 + nt*8 + 2*c4l;
                    float2 v;
                    v.x = acc[mt][nt][half*2+0] + bias[dcol];
                    v.y = acc[mt][nt][half*2+1] + bias[dcol+1];
                    *(float2*)(orow + dcol) = v;
                }
            }
        }
    }
}

// ---------------- launch ----------------
extern "C" void kernel_launch(void* const* d_in, const int* in_sizes, int n_in,
                              void* d_out, int out_size) {
    const float* st       = (const float*)d_in[0];   // slice_token
    const float* sw       = (const float*)d_in[1];   // slice_weights
    const float* w_in     = (const float*)d_in[2];
    const float* conv_w   = (const float*)d_in[3];
    const float* conv_b   = (const float*)d_in[4];
    const float* dt_bias  = (const float*)d_in[5];
    const float* A_log    = (const float*)d_in[6];
    const float* Dp       = (const float*)d_in[7];
    const float* fcD      = (const float*)d_in[8];
    const float* norm_w   = (const float*)d_in[9];
    const float* w_out    = (const float*)d_in[10];
    const float* to_out_w = (const float*)d_in[11];
    const float* to_out_b = (const float*)d_in[12];

    float* out      = (float*)d_out;
    float* inp_seg  = out + (size_t)FINAL_ELEMS;
    float* outp_seg = out + (size_t)FINAL_ELEMS + INP_ELEMS;

    float *p_u, *p_zx, *p_y, *p_o;
    cudaGetSymbolAddress((void**)&p_u,  g_u);
    cudaGetSymbolAddress((void**)&p_zx, g_zx);
    cudaGetSymbolAddress((void**)&p_y,  g_y);
    cudaGetSymbolAddress((void**)&p_o,  g_o);

    const int DSMEM = 2 * STG_BYTES;   // 73728 B
    cudaFuncSetAttribute(k_gemm_final_mma,
                         cudaFuncAttributeMaxDynamicSharedMemorySize, DSMEM);

    // 0. sw -> tf32-rounded copy (independent; do it first)
    k_round_sw<<<(SW_ELEMS/4 + 255)/256, 256>>>(sw);
    // 1. gather u
    k_build_u<<<(ROWS*DM + 255)/256, 256>>>(st);
    // 2. in-projection: zx = u @ w_in^T  (1024 x 1042, K=512)
    k_gemm_nt<<<dim3((DINPROJ + 63)/64, ROWS/64), 256>>>(
        p_u, DM, w_in, DM, p_zx, DINPROJ, ROWS, DINPROJ, DM);
    // 3. dt activations
    k_dt<<<(ROWS*NH + 255)/256, 256>>>(dt_bias);
    // 4. conv + silu + split
    k_conv<<<(ROWS*CONVDIM + 255)/256, 256>>>(conv_w, conv_b);
    // 5. dcoef
    k_dcoef<<<ROWS, 256>>>(fcD, Dp);
    // 6. bidirectional scan (+ D-term + silu(z) gate)
    k_scan<<<dim3(HEADS, B_), 64>>>(A_log);
    // 7. RMS norm
    k_norm<<<ROWS, 256>>>(norm_w);
    // 8. out = y @ w_out^T  (1024 x 512, K=512)
    k_gemm_nt<<<dim3(DM/64, ROWS/64), 256>>>(
        p_y, DM, w_out, DM, p_o, DM, ROWS, DM, DM);
    // 9. outp layout + write segment 3
    k_outp<<<(INP_ELEMS + 255)/256, 256>>>(outp_seg);
    // 10. inp passthrough (segment 2)
    cudaMemcpyAsync(inp_seg, st, (size_t)INP_ELEMS * sizeof(float),
                    cudaMemcpyDeviceToDevice);
    // 11. M2T = per-(b,h) outp @ to_out_w_block^T -> tf32-rounded K-major
    k_gemm_m2<<<dim3(8, 1, B_*HEADS), 256>>>(to_out_w);
    // 12. final = SW @ M2 + bias via tf32 mma (16 x 3131x512x512)
    k_gemm_final_mma<<<dim3(DM/128, (NSEQ + 127)/128, B_), 256, DSMEM>>>(
        to_out_b, out);
}

// round 14
// speedup vs baseline: 2.7216x; 1.0121x over previous
#include <cuda_runtime.h>
#include <cuda_bf16.h>
#include <math.h>
#include <stdint.h>

// ---------------- problem constants ----------------
#define B_      16
#define HEADS   8
#define G_      64
#define DH      64
#define NSEQ    3131            // 101*31
#define DM      512
#define NH      8
#define L       64
#define DINPROJ 1042            // 2*DM + 2 + 16
#define CONVDIM 514
#define ROWS    1024            // B_*L

#define FINAL_ELEMS (B_*NSEQ*DM)        // 25,649,152
#define INP_ELEMS   (B_*HEADS*G_*DH)    //    524,288

// ---------------- scratch (device globals; no allocs) ----------------
__device__ float g_zx[ROWS*DINPROJ];
__device__ float g_x[ROWS*DM];
__device__ float g_Bv[ROWS];
__device__ float g_Cv[ROWS];
__device__ float g_dtfw[ROWS*NH];
__device__ float g_dtbw[ROWS*NH];
__device__ float g_dcoef[ROWS*NH];
__device__ float g_y[ROWS*DM];
__device__ float g_o[ROWS*DM];
__device__ float g_outp[B_*HEADS*G_*DH];
__device__ __align__(16) float g_m2t[B_*DM*DM];    // [b][d][k] K-major, tf32-rounded

// ---------------- small helpers ----------------
__device__ __forceinline__ float softplus_f(float x) {
    return fmaxf(x, 0.f) + log1pf(expf(-fabsf(x)));
}
__device__ __forceinline__ float silu_f(float x) {
    return x / (1.f + expf(-x));
}
__device__ __forceinline__ uint32_t smem_u32(const void* p) {
    uint32_t a;
    asm("{ .reg .u64 t; cvta.to.shared.u64 t, %1; cvt.u32.u64 %0, t; }"
        : "=r"(a) : "l"(p));
    return a;
}
__device__ __forceinline__ float tf32_rna(float x) {
    uint32_t t;
    asm("cvt.rna.tf32.f32 %0, %1;" : "=r"(t) : "f"(x));
    return __uint_as_float(t);
}
__device__ __forceinline__ void cp_async16(uint32_t dst, const void* src, uint32_t sz) {
    asm volatile("cp.async.ca.shared.global [%0], [%1], 16, %2;"
                 :: "r"(dst), "l"(src), "r"(sz) : "memory");
}
#define CP_COMMIT() asm volatile("cp.async.commit_group;" ::: "memory")

__device__ __forceinline__ void mma_tf32(float* c, const uint32_t* a, const uint32_t* b) {
    asm volatile("mma.sync.aligned.m16n8k8.row.col.f32.tf32.tf32.f32 "
                 "{%0,%1,%2,%3}, {%4,%5,%6,%7}, {%8,%9}, {%0,%1,%2,%3};"
                 : "+f"(c[0]), "+f"(c[1]), "+f"(c[2]), "+f"(c[3])
                 : "r"(a[0]), "r"(a[1]), "r"(a[2]), "r"(a[3]),
                   "r"(b[0]), "r"(b[1]));
}

// ---------------- kernels ----------------

// In-projection GEMM with fused slice_token gather:
// zx[m, n] = sum_k u[m,k]*w_in[n,k],  u[b*64+l, h*64+c] = st[b,h,l,c]
__global__ void k_gemm_inproj(const float* __restrict__ st,
                              const float* __restrict__ w_in) {
    __shared__ float As[16][68];
    __shared__ float Bs[16][68];
    int tid = threadIdx.x;
    int m0 = blockIdx.y * 64, n0 = blockIdx.x * 64;
    int r  = tid >> 2;
    int c4 = (tid & 3) * 4;
    int ty = tid >> 4, tx = tid & 15;
    int row = m0 + r;
    int bb = row >> 6, ll = row & 63;
    float acc[4][4] = {};
    for (int kt = 0; kt < DM; kt += 16) {
        int k = kt + c4;
        int h = k >> 6, c = k & 63;
        // gather A directly from slice_token (float4 stays within one head)
        float4 av = *(const float4*)(st + (((size_t)(bb*HEADS + h)*G_ + ll)*DH) + c);
        As[c4+0][r]=av.x; As[c4+1][r]=av.y; As[c4+2][r]=av.z; As[c4+3][r]=av.w;
        float4 bv = make_float4(0.f,0.f,0.f,0.f);
        if (n0 + r < DINPROJ) bv = *(const float4*)(w_in + (size_t)(n0 + r)*DM + kt + c4);
        Bs[c4+0][r]=bv.x; Bs[c4+1][r]=bv.y; Bs[c4+2][r]=bv.z; Bs[c4+3][r]=bv.w;
        __syncthreads();
#pragma unroll
        for (int kk = 0; kk < 16; kk++) {
            float a[4], b[4];
#pragma unroll
            for (int i = 0; i < 4; i++) a[i] = As[kk][ty*4 + i];
#pragma unroll
            for (int j = 0; j < 4; j++) b[j] = Bs[kk][tx*4 + j];
#pragma unroll
            for (int i = 0; i < 4; i++)
#pragma unroll
                for (int j = 0; j < 4; j++) acc[i][j] += a[i]*b[j];
        }
        __syncthreads();
    }
#pragma unroll
    for (int i = 0; i < 4; i++) {
        int m = m0 + ty*4 + i;
#pragma unroll
        for (int j = 0; j < 4; j++) {
            int n = n0 + tx*4 + j;
            if (n < DINPROJ)
                g_zx[(size_t)m*DINPROJ + n] = acc[i][j];
        }
    }
}

// Generic NT GEMM (scalar fp32): C[m,n] = sum_k A[m,k]*B[n,k]
__global__ void k_gemm_nt(const float* __restrict__ A, int lda,
                          const float* __restrict__ Bm, int ldb,
                          float* __restrict__ C, int ldc,
                          int M, int N, int K) {
    __shared__ float As[16][68];
    __shared__ float Bs[16][68];
    int tid = threadIdx.x;
    int m0 = blockIdx.y * 64, n0 = blockIdx.x * 64;
    int r  = tid >> 2;
    int c4 = (tid & 3) * 4;
    int ty = tid >> 4, tx = tid & 15;
    float acc[4][4] = {};
    for (int kt = 0; kt < K; kt += 16) {
        float4 av = make_float4(0.f,0.f,0.f,0.f);
        if (m0 + r < M) av = *(const float4*)(A + (size_t)(m0 + r)*lda + kt + c4);
        As[c4+0][r]=av.x; As[c4+1][r]=av.y; As[c4+2][r]=av.z; As[c4+3][r]=av.w;
        float4 bv = make_float4(0.f,0.f,0.f,0.f);
        if (n0 + r < N) bv = *(const float4*)(Bm + (size_t)(n0 + r)*ldb + kt + c4);
        Bs[c4+0][r]=bv.x; Bs[c4+1][r]=bv.y; Bs[c4+2][r]=bv.z; Bs[c4+3][r]=bv.w;
        __syncthreads();
#pragma unroll
        for (int kk = 0; kk < 16; kk++) {
            float a[4], b[4];
#pragma unroll
            for (int i = 0; i < 4; i++) a[i] = As[kk][ty*4 + i];
#pragma unroll
            for (int j = 0; j < 4; j++) b[j] = Bs[kk][tx*4 + j];
#pragma unroll
            for (int i = 0; i < 4; i++)
#pragma unroll
                for (int j = 0; j < 4; j++) acc[i][j] += a[i]*b[j];
        }
        __syncthreads();
    }
#pragma unroll
    for (int i = 0; i < 4; i++) {
        int m = m0 + ty*4 + i;
        if (m >= M) continue;
#pragma unroll
        for (int j = 0; j < 4; j++) {
            int n = n0 + tx*4 + j;
            if (n >= N) continue;
            C[(size_t)m*ldc + n] = acc[i][j];
        }
    }
}

// dt fw/bw: softplus(raw + dt_bias)
__global__ void k_dt(const float* __restrict__ dt_bias) {
    int idx = blockIdx.x * blockDim.x + threadIdx.x;
    if (idx >= ROWS*NH) return;
    int h = idx & 7, row = idx >> 3;
    float bsh = dt_bias[h];
    float vf = g_zx[(size_t)row*DINPROJ + 1026 + h] + bsh;
    float vb = g_zx[(size_t)row*DINPROJ + 1034 + h] + bsh;
    g_dtfw[idx] = softplus_f(vf);
    g_dtbw[idx] = softplus_f(vb);
}

// depthwise causal conv (width 3) + silu; split x / Bv / Cv
__global__ void k_conv(const float* __restrict__ conv_w,
                       const float* __restrict__ conv_b) {
    int idx = blockIdx.x * blockDim.x + threadIdx.x;
    if (idx >= ROWS*CONVDIM) return;
    int ch  = idx % CONVDIM;
    int row = idx / CONVDIM;
    int b = row >> 6, l = row & 63;
    float acc = conv_b[ch];
#pragma unroll
    for (int k = 0; k < 3; k++) {
        int lp = l + k - 2;
        if (lp >= 0)
            acc += conv_w[ch*3 + k] * g_zx[(size_t)((b<<6) + lp)*DINPROJ + 512 + ch];
    }
    float s = silu_f(acc);
    if (ch < 512)       g_x[(size_t)row*512 + ch] = s;
    else if (ch == 512) g_Bv[row] = s;
    else                g_Cv[row] = s;
}

// dcoef[row,h] = x[row,:] . fc_D_w[h,:] + D[h]
__global__ void k_dcoef(const float* __restrict__ fcD,
                        const float* __restrict__ Dp) {
    int row  = blockIdx.x;
    int w    = threadIdx.x >> 5;
    int lane = threadIdx.x & 31;
    const float* xr = g_x + (size_t)row*512;
    const float* fr = fcD + (size_t)w*512;
    float s = 0.f;
    for (int k = lane; k < 512; k += 32) s += xr[k]*fr[k];
#pragma unroll
    for (int o = 16; o > 0; o >>= 1) s += __shfl_down_sync(0xffffffffu, s, o);
    if (lane == 0) g_dcoef[row*8 + w] = s + Dp[w];
}

// bidirectional SSM scan
__global__ void k_scan(const float* __restrict__ A_log) {
    int h = blockIdx.x, b = blockIdx.y;
    int tid = threadIdx.x;
    __shared__ float s_afw[L], s_bfw[L], s_abw[L], s_bbw[L], s_C[L];
    __shared__ float s_acc[64][65];
    {
        int l = tid;
        int row = (b<<6) + l;
        float Ah  = -expf(A_log[h]);
        float dtf = g_dtfw[row*8 + h];
        float dtb = g_dtbw[row*8 + h];
        float Bl  = g_Bv[row];
        s_afw[l] = expf(dtf*Ah); s_bfw[l] = dtf*Bl;
        s_abw[l] = expf(dtb*Ah); s_bbw[l] = dtb*Bl;
        s_C[l]   = g_Cv[row];
    }
    __syncthreads();
    int d = tid;
    const float* xcol = g_x + (size_t)(b<<6)*512 + h*64 + d;
    float state = 0.f, cprev = 0.f;
    for (int l = 0; l < L; l++) {
        s_acc[d][l] = state * cprev;
        float xv = xcol[(size_t)l*512];
        state = s_afw[l]*state + s_bfw[l]*xv;
        cprev = s_C[l];
    }
    state = 0.f; cprev = 0.f;
    for (int lr = 0; lr < L; lr++) {
        int lo = 63 - lr;
        float xv = xcol[(size_t)lo*512];
        s_acc[d][lo] += state * cprev;
        state = s_abw[lo]*state + s_bbw[lo]*xv;
        cprev = s_C[lo];
    }
    for (int l = 0; l < L; l++) {
        int row = (b<<6) + l;
        float xv = xcol[(size_t)l*512];
        float v  = s_acc[d][l] + xv * g_dcoef[row*8 + h];
        float z  = g_zx[(size_t)row*DINPROJ + h*64 + d];
        v *= silu_f(z);
        g_y[(size_t)row*512 + h*64 + d] = v;
    }
}

// RMS norm * norm_w, in-place on g_y
__global__ void k_norm(const float* __restrict__ norm_w) {
    int row = blockIdx.x;
    float* yr = g_y + (size_t)row*512;
    int tid = threadIdx.x;                 // 256
    float v0 = yr[tid], v1 = yr[tid + 256];
    float s = v0*v0 + v1*v1;
    __shared__ float red[8];
#pragma unroll
    for (int o = 16; o > 0; o >>= 1) s += __shfl_down_sync(0xffffffffu, s, o);
    if ((tid & 31) == 0) red[tid >> 5] = s;
    __syncthreads();
    if (tid < 32) {
        float t = (tid < 8) ? red[tid] : 0.f;
#pragma unroll
        for (int o = 4; o > 0; o >>= 1) t += __shfl_down_sync(0xffffffffu, t, o);
        if (tid == 0) red[0] = t;
    }
    __syncthreads();
    float scale = rsqrtf(red[0] * (1.f/512.f) + 1e-5f);
    yr[tid]       = v0 * scale * norm_w[tid];
    yr[tid + 256] = v1 * scale * norm_w[tid + 256];
}

// outp[b,h,g,c] = g_o[(b*64+g)*512 + h*64+c]; also writes output segment 3
__global__ void k_outp(float* __restrict__ out_seg) {
    int idx = blockIdx.x * blockDim.x + threadIdx.x;
    if (idx >= INP_ELEMS) return;
    int c = idx & 63;
    int g = (idx >> 6) & 63;
    int h = (idx >> 12) & 7;
    int b = idx >> 15;
    float v = g_o[(size_t)((b<<6) + g)*512 + h*64 + c];
    g_outp[idx] = v;
    out_seg[idx] = v;
}

// M2T[b, d, h*64+g] = sum_c outp[b,h,g,c]*to_out_w[d, h*64+c]
// epilogue stores tf32-rounded fp32 K-major
__global__ void k_gemm_m2(const float* __restrict__ to_out_w) {
    int z = blockIdx.z; int b = z >> 3, h = z & 7;
    const float* A  = g_outp + (size_t)z * 4096;                 // 64x64 (g,c)
    const float* Bm = to_out_w + h*64;                           // rows d, ldb 512
    __shared__ float As[16][68];
    __shared__ float Bs[16][68];
    int tid = threadIdx.x;
    int n0 = blockIdx.x * 64;    // over d
    int r = tid >> 2, c4 = (tid & 3) * 4;
    int ty = tid >> 4, tx = tid & 15;
    float acc[4][4] = {};
    for (int kt = 0; kt < 64; kt += 16) {
        float4 av = *(const float4*)(A + (size_t)r*64 + kt + c4);
        As[c4+0][r]=av.x; As[c4+1][r]=av.y; As[c4+2][r]=av.z; As[c4+3][r]=av.w;
        float4 bv = *(const float4*)(Bm + (size_t)(n0 + r)*512 + kt + c4);
        Bs[c4+0][r]=bv.x; Bs[c4+1][r]=bv.y; Bs[c4+2][r]=bv.z; Bs[c4+3][r]=bv.w;
        __syncthreads();
#pragma unroll
        for (int kk = 0; kk < 16; kk++) {
            float a[4], bb[4];
#pragma unroll
            for (int i = 0; i < 4; i++) a[i] = As[kk][ty*4 + i];
#pragma unroll
            for (int j = 0; j < 4; j++) bb[j] = Bs[kk][tx*4 + j];
#pragma unroll
            for (int i = 0; i < 4; i++)
#pragma unroll
                for (int j = 0; j < 4; j++) acc[i][j] += a[i]*bb[j];
        }
        __syncthreads();
    }
    // transposed store (row = d, col = k = h*64 + g), tf32-rounded
#pragma unroll
    for (int i = 0; i < 4; i++)
#pragma unroll
        for (int j = 0; j < 4; j++) {
            size_t o = (size_t)b*262144
                     + (size_t)(n0 + tx*4 + j)*512 + (h*64 + ty*4 + i);
            g_m2t[o] = tf32_rna(acc[i][j]);
        }
}

// ================= TF32 MMA big GEMM =================
// final[b,n,d] = sum_k sw[b,n,k]*M2T[b,d,k] + bias[d]
// Tile 128(n) x 128(d), BK=32, 8 warps (warp tile 64x32), cp.async 3-stage.
// A = raw fp32 sw (HW truncates to tf32), B = m2t (RNA tf32-rounded).
// smem: fp32 tiles, row stride 36 floats (conflict-free scalar LDS fragments).
#define STG_A_BYTES 18432          // 128 rows * 144 B
#define STG_BYTES   36864          // A + B
#define N_STAGES    3
__global__ void __launch_bounds__(256)
k_gemm_final_mma(const float* __restrict__ swp,
                 const float* __restrict__ bias, float* __restrict__ out) {
    extern __shared__ __align__(16) char dsm[];
    uint32_t sbase = smem_u32(dsm);

    int tid = threadIdx.x;
    int lane = tid & 31, warp = tid >> 5;
    int wm = warp >> 2, wn = warp & 3;          // 2 x 4 warp grid
    int b  = blockIdx.z;
    int d0 = blockIdx.x * 128;
    int n0 = blockIdx.y * 128;

    const size_t swoff = (size_t)b * HEADS * NSEQ * 64;
    const size_t m2off = (size_t)b * 262144;

    float acc[4][4][4] = {};    // [mt][nt][frag]

#define ISSUE_LOADS(it, buf) do {                                           \
    int kt_ = (it) * 32;                                                    \
    int h_  = kt_ >> 6, k64_ = kt_ & 63;                                    \
    uint32_t base_ = sbase + (buf) * STG_BYTES;                             \
    _Pragma("unroll")                                                       \
    for (int i_ = 0; i_ < 4; i_++) {                                        \
        int id_  = tid + 256 * i_;            /* 0..1023 */                 \
        int row_ = id_ >> 3, c_ = id_ & 7;                                  \
        uint32_t doff_ = (uint32_t)(row_ * 144 + c_ * 16);                  \
        int n_ = n0 + row_;                                                 \
        int nc_ = (n_ < NSEQ) ? n_ : (NSEQ - 1);                            \
        uint32_t sz_ = (n_ < NSEQ) ? 16u : 0u;                              \
        size_t aoff_ = swoff + (((size_t)h_*NSEQ + nc_)*64 + k64_ + c_*4);  \
        cp_async16(base_ + doff_, swp + aoff_, sz_);                        \
        int d_ = d0 + row_;                                                 \
        size_t boff_ = m2off + ((size_t)d_*512 + kt_ + c_*4);               \
        cp_async16(base_ + STG_A_BYTES + doff_, g_m2t + boff_, 16u);        \
    }                                                                       \
    CP_COMMIT();                                                            \
} while (0)

    int r4  = lane >> 2;
    int c4l = lane & 3;

    ISSUE_LOADS(0, 0);
    ISSUE_LOADS(1, 1);
    for (int it = 0; it < 16; it++) {
        int buf = it % N_STAGES;
        if (it + 2 < 16)
            asm volatile("cp.async.wait_group 1;" ::: "memory");
        else
            asm volatile("cp.async.wait_group 0;" ::: "memory");
        __syncthreads();
        if (it + 2 < 16) ISSUE_LOADS(it + 2, (it + 2) % N_STAGES);

        const float* As = (const float*)(dsm + buf * STG_BYTES);
        const float* Bs = (const float*)(dsm + buf * STG_BYTES + STG_A_BYTES);

#pragma unroll
        for (int ks = 0; ks < 4; ks++) {
            int col = ks * 8 + c4l;
            uint32_t af[4][4];
#pragma unroll
            for (int mt = 0; mt < 4; mt++) {
                int row = wm*64 + mt*16 + r4;
                af[mt][0] = __float_as_uint(As[row*36 + col]);
                af[mt][1] = __float_as_uint(As[(row+8)*36 + col]);
                af[mt][2] = __float_as_uint(As[row*36 + col + 4]);
                af[mt][3] = __float_as_uint(As[(row+8)*36 + col + 4]);
            }
            uint32_t bf[4][2];
#pragma unroll
            for (int nt = 0; nt < 4; nt++) {
                int n = wn*32 + nt*8 + r4;
                bf[nt][0] = __float_as_uint(Bs[n*36 + col]);
                bf[nt][1] = __float_as_uint(Bs[n*36 + col + 4]);
            }
#pragma unroll
            for (int mt = 0; mt < 4; mt++)
#pragma unroll
                for (int nt = 0; nt < 4; nt++)
                    mma_tf32(acc[mt][nt], af[mt], bf[nt]);
        }
        __syncthreads();
    }
#undef ISSUE_LOADS

    // ---- epilogue ----
#pragma unroll
    for (int mt = 0; mt < 4; mt++) {
        int rbase = n0 + wm*64 + mt*16 + r4;
#pragma unroll
        for (int half = 0; half < 2; half++) {
            int n = rbase + half*8;
            if (n < NSEQ) {
                float* orow = out + ((size_t)b*NSEQ + n)*512;
#pragma unroll
                for (int nt = 0; nt < 4; nt++) {
                    int dcol = d0 + wn*32 + nt*8 + 2*c4l;
                    float2 v;
                    v.x = acc[mt][nt][half*2+0] + bias[dcol];
                    v.y = acc[mt][nt][half*2+1] + bias[dcol+1];
                    *(float2*)(orow + dcol) = v;
                }
            }
        }
    }
}

// ---------------- launch ----------------
extern "C" void kernel_launch(void* const* d_in, const int* in_sizes, int n_in,
                              void* d_out, int out_size) {
    const float* st       = (const float*)d_in[0];   // slice_token
    const float* sw       = (const float*)d_in[1];   // slice_weights
    const float* w_in     = (const float*)d_in[2];
    const float* conv_w   = (const float*)d_in[3];
    const float* conv_b   = (const float*)d_in[4];
    const float* dt_bias  = (const float*)d_in[5];
    const float* A_log    = (const float*)d_in[6];
    const float* Dp       = (const float*)d_in[7];
    const float* fcD      = (const float*)d_in[8];
    const float* norm_w   = (const float*)d_in[9];
    const float* w_out    = (const float*)d_in[10];
    const float* to_out_w = (const float*)d_in[11];
    const float* to_out_b = (const float*)d_in[12];

    float* out      = (float*)d_out;
    float* inp_seg  = out + (size_t)FINAL_ELEMS;
    float* outp_seg = out + (size_t)FINAL_ELEMS + INP_ELEMS;

    float *p_y, *p_o;
    cudaGetSymbolAddress((void**)&p_y, g_y);
    cudaGetSymbolAddress((void**)&p_o, g_o);

    const int DSMEM = N_STAGES * STG_BYTES;   // 110592 B
    cudaFuncSetAttribute(k_gemm_final_mma,
                         cudaFuncAttributeMaxDynamicSharedMemorySize, DSMEM);

    // 1. in-projection with fused slice_token gather (1024 x 1042, K=512)
    k_gemm_inproj<<<dim3((DINPROJ + 63)/64, ROWS/64), 256>>>(st, w_in);
    // 2. dt activations
    k_dt<<<(ROWS*NH + 255)/256, 256>>>(dt_bias);
    // 3. conv + silu + split
    k_conv<<<(ROWS*CONVDIM + 255)/256, 256>>>(conv_w, conv_b);
    // 4. dcoef
    k_dcoef<<<ROWS, 256>>>(fcD, Dp);
    // 5. bidirectional scan (+ D-term + silu(z) gate)
    k_scan<<<dim3(HEADS, B_), 64>>>(A_log);
    // 6. RMS norm
    k_norm<<<ROWS, 256>>>(norm_w);
    // 7. out = y @ w_out^T  (1024 x 512, K=512)
    k_gemm_nt<<<dim3(DM/64, ROWS/64), 256>>>(
        p_y, DM, w_out, DM, p_o, DM, ROWS, DM, DM);
    // 8. outp layout + write segment 3
    k_outp<<<(INP_ELEMS + 255)/256, 256>>>(outp_seg);
    // 9. inp passthrough (segment 2)
    cudaMemcpyAsync(inp_seg, st, (size_t)INP_ELEMS * sizeof(float),
                    cudaMemcpyDeviceToDevice);
    // 10. M2T = per-(b,h) outp @ to_out_w_block^T -> tf32-rounded K-major
    k_gemm_m2<<<dim3(8, 1, B_*HEADS), 256>>>(to_out_w);
    // 11. final = SW @ M2 + bias via tf32 mma (16 x 3131x512x512)
    k_gemm_final_mma<<<dim3(DM/128, (NSEQ + 127)/128, B_), 256, DSMEM>>>(
        sw, to_out_b, out);
}

// round 16
// speedup vs baseline: 3.0442x; 1.1185x over previous
#include <cuda_runtime.h>
#include <cuda_bf16.h>
#include <math.h>
#include <stdint.h>

// ---------------- problem constants ----------------
#define B_      16
#define HEADS   8
#define G_      64
#define DH      64
#define NSEQ    3131            // 101*31
#define DM      512
#define NH      8
#define L       64
#define DINPROJ 1042            // 2*DM + 2 + 16
#define CONVDIM 514
#define ROWS    1024            // B_*L

#define FINAL_ELEMS (B_*NSEQ*DM)        // 25,649,152
#define INP_ELEMS   (B_*HEADS*G_*DH)    //    524,288

// ---------------- scratch (device globals; no allocs) ----------------
__device__ float g_zx[ROWS*DINPROJ];
__device__ float g_x[ROWS*DM];
__device__ float g_Bv[ROWS];
__device__ float g_Cv[ROWS];
__device__ float g_dtfw[ROWS*NH];
__device__ float g_dtbw[ROWS*NH];
__device__ float g_dcoef[ROWS*NH];
__device__ float g_y[ROWS*DM];
__device__ float g_outp[B_*HEADS*G_*DH];
__device__ __align__(16) float g_m2t[B_*DM*DM];    // [b][d][k] K-major, tf32-rounded

// ---------------- small helpers ----------------
__device__ __forceinline__ float softplus_f(float x) {
    return fmaxf(x, 0.f) + log1pf(expf(-fabsf(x)));
}
__device__ __forceinline__ float silu_f(float x) {
    return x / (1.f + expf(-x));
}
__device__ __forceinline__ uint32_t smem_u32(const void* p) {
    uint32_t a;
    asm("{ .reg .u64 t; cvta.to.shared.u64 t, %1; cvt.u32.u64 %0, t; }"
        : "=r"(a) : "l"(p));
    return a;
}
__device__ __forceinline__ float tf32_rna(float x) {
    uint32_t t;
    asm("cvt.rna.tf32.f32 %0, %1;" : "=r"(t) : "f"(x));
    return __uint_as_float(t);
}
__device__ __forceinline__ void cp_async16(uint32_t dst, const void* src, uint32_t sz) {
    asm volatile("cp.async.ca.shared.global [%0], [%1], 16, %2;"
                 :: "r"(dst), "l"(src), "r"(sz) : "memory");
}
#define CP_COMMIT() asm volatile("cp.async.commit_group;" ::: "memory")

__device__ __forceinline__ void mma_tf32(float* c, const uint32_t* a, const uint32_t* b) {
    asm volatile("mma.sync.aligned.m16n8k8.row.col.f32.tf32.tf32.f32 "
                 "{%0,%1,%2,%3}, {%4,%5,%6,%7}, {%8,%9}, {%0,%1,%2,%3};"
                 : "+f"(c[0]), "+f"(c[1]), "+f"(c[2]), "+f"(c[3])
                 : "r"(a[0]), "r"(a[1]), "r"(a[2]), "r"(a[3]),
                   "r"(b[0]), "r"(b[1]));
}

// ---------------- kernels ----------------

// In-projection GEMM with fused slice_token gather:
// zx[m, n] = sum_k u[m,k]*w_in[n,k],  u[b*64+l, h*64+c] = st[b,h,l,c]
__global__ void k_gemm_inproj(const float* __restrict__ st,
                              const float* __restrict__ w_in) {
    __shared__ float As[16][68];
    __shared__ float Bs[16][68];
    int tid = threadIdx.x;
    int m0 = blockIdx.y * 64, n0 = blockIdx.x * 64;
    int r  = tid >> 2;
    int c4 = (tid & 3) * 4;
    int ty = tid >> 4, tx = tid & 15;
    int row = m0 + r;
    int bb = row >> 6, ll = row & 63;
    float acc[4][4] = {};
    for (int kt = 0; kt < DM; kt += 16) {
        int k = kt + c4;
        int h = k >> 6, c = k & 63;
        float4 av = *(const float4*)(st + (((size_t)(bb*HEADS + h)*G_ + ll)*DH) + c);
        As[c4+0][r]=av.x; As[c4+1][r]=av.y; As[c4+2][r]=av.z; As[c4+3][r]=av.w;
        float4 bv = make_float4(0.f,0.f,0.f,0.f);
        if (n0 + r < DINPROJ) bv = *(const float4*)(w_in + (size_t)(n0 + r)*DM + kt + c4);
        Bs[c4+0][r]=bv.x; Bs[c4+1][r]=bv.y; Bs[c4+2][r]=bv.z; Bs[c4+3][r]=bv.w;
        __syncthreads();
#pragma unroll
        for (int kk = 0; kk < 16; kk++) {
            float a[4], b[4];
#pragma unroll
            for (int i = 0; i < 4; i++) a[i] = As[kk][ty*4 + i];
#pragma unroll
            for (int j = 0; j < 4; j++) b[j] = Bs[kk][tx*4 + j];
#pragma unroll
            for (int i = 0; i < 4; i++)
#pragma unroll
                for (int j = 0; j < 4; j++) acc[i][j] += a[i]*b[j];
        }
        __syncthreads();
    }
#pragma unroll
    for (int i = 0; i < 4; i++) {
        int m = m0 + ty*4 + i;
#pragma unroll
        for (int j = 0; j < 4; j++) {
            int n = n0 + tx*4 + j;
            if (n < DINPROJ)
                g_zx[(size_t)m*DINPROJ + n] = acc[i][j];
        }
    }
}

// w_out GEMM with fused outp-layout epilogue:
// v[m,n] = sum_k y[m,k]*w_out[n,k];  m=b*64+g, n=h*64+c
// writes g_outp[b,h,g,c] and output segment 3 directly.
__global__ void k_gemm_wout(const float* __restrict__ w_out,
                            float* __restrict__ out_seg) {
    __shared__ float As[16][68];
    __shared__ float Bs[16][68];
    int tid = threadIdx.x;
    int m0 = blockIdx.y * 64, n0 = blockIdx.x * 64;
    int r  = tid >> 2;
    int c4 = (tid & 3) * 4;
    int ty = tid >> 4, tx = tid & 15;
    float acc[4][4] = {};
    for (int kt = 0; kt < DM; kt += 16) {
        float4 av = *(const float4*)(g_y + (size_t)(m0 + r)*DM + kt + c4);
        As[c4+0][r]=av.x; As[c4+1][r]=av.y; As[c4+2][r]=av.z; As[c4+3][r]=av.w;
        float4 bv = *(const float4*)(w_out + (size_t)(n0 + r)*DM + kt + c4);
        Bs[c4+0][r]=bv.x; Bs[c4+1][r]=bv.y; Bs[c4+2][r]=bv.z; Bs[c4+3][r]=bv.w;
        __syncthreads();
#pragma unroll
        for (int kk = 0; kk < 16; kk++) {
            float a[4], b[4];
#pragma unroll
            for (int i = 0; i < 4; i++) a[i] = As[kk][ty*4 + i];
#pragma unroll
            for (int j = 0; j < 4; j++) b[j] = Bs[kk][tx*4 + j];
#pragma unroll
            for (int i = 0; i < 4; i++)
#pragma unroll
                for (int j = 0; j < 4; j++) acc[i][j] += a[i]*b[j];
        }
        __syncthreads();
    }
#pragma unroll
    for (int i = 0; i < 4; i++) {
        int m = m0 + ty*4 + i;
        int bb = m >> 6, g = m & 63;
#pragma unroll
        for (int j = 0; j < 4; j++) {
            int n = n0 + tx*4 + j;
            int h = n >> 6, c = n & 63;
            size_t o = (((size_t)(bb*HEADS + h)*G_ + g)*DH) + c;
            float v = acc[i][j];
            g_outp[o]  = v;
            out_seg[o] = v;
        }
    }
}

// fused dt + depthwise causal conv (width 3) + silu; split x / Bv / Cv
__global__ void k_conv(const float* __restrict__ conv_w,
                       const float* __restrict__ conv_b,
                       const float* __restrict__ dt_bias) {
    int idx = blockIdx.x * blockDim.x + threadIdx.x;
    // fused dt path (first ROWS*NH threads)
    if (idx < ROWS*NH) {
        int h = idx & 7, row = idx >> 3;
        float bsh = dt_bias[h];
        float vf = g_zx[(size_t)row*DINPROJ + 1026 + h] + bsh;
        float vb = g_zx[(size_t)row*DINPROJ + 1034 + h] + bsh;
        g_dtfw[idx] = softplus_f(vf);
        g_dtbw[idx] = softplus_f(vb);
    }
    if (idx >= ROWS*CONVDIM) return;
    int ch  = idx % CONVDIM;
    int row = idx / CONVDIM;
    int b = row >> 6, l = row & 63;
    float acc = conv_b[ch];
#pragma unroll
    for (int k = 0; k < 3; k++) {
        int lp = l + k - 2;
        if (lp >= 0)
            acc += conv_w[ch*3 + k] * g_zx[(size_t)((b<<6) + lp)*DINPROJ + 512 + ch];
    }
    float s = silu_f(acc);
    if (ch < 512)       g_x[(size_t)row*512 + ch] = s;
    else if (ch == 512) g_Bv[row] = s;
    else                g_Cv[row] = s;
}

// dcoef[row,h] = x[row,:] . fc_D_w[h,:] + D[h]   (float4, 8 warps per row)
__global__ void k_dcoef(const float* __restrict__ fcD,
                        const float* __restrict__ Dp) {
    int row  = blockIdx.x;
    int w    = threadIdx.x >> 5;
    int lane = threadIdx.x & 31;
    const float4* xr = (const float4*)(g_x + (size_t)row*512);
    const float4* fr = (const float4*)(fcD + (size_t)w*512);
    float s = 0.f;
#pragma unroll
    for (int i = 0; i < 4; i++) {
        float4 xv = xr[lane + 32*i];
        float4 fv = fr[lane + 32*i];
        s += xv.x*fv.x + xv.y*fv.y + xv.z*fv.z + xv.w*fv.w;
    }
#pragma unroll
    for (int o = 16; o > 0; o >>= 1) s += __shfl_down_sync(0xffffffffu, s, o);
    if (lane == 0) g_dcoef[row*8 + w] = s + Dp[w];
}

// bidirectional SSM scan
__global__ void k_scan(const float* __restrict__ A_log) {
    int h = blockIdx.x, b = blockIdx.y;
    int tid = threadIdx.x;
    __shared__ float s_afw[L], s_bfw[L], s_abw[L], s_bbw[L], s_C[L];
    __shared__ float s_acc[64][65];
    {
        int l = tid;
        int row = (b<<6) + l;
        float Ah  = -expf(A_log[h]);
        float dtf = g_dtfw[row*8 + h];
        float dtb = g_dtbw[row*8 + h];
        float Bl  = g_Bv[row];
        s_afw[l] = expf(dtf*Ah); s_bfw[l] = dtf*Bl;
        s_abw[l] = expf(dtb*Ah); s_bbw[l] = dtb*Bl;
        s_C[l]   = g_Cv[row];
    }
    __syncthreads();
    int d = tid;
    const float* xcol = g_x + (size_t)(b<<6)*512 + h*64 + d;
    float state = 0.f, cprev = 0.f;
    for (int l = 0; l < L; l++) {
        s_acc[d][l] = state * cprev;
        float xv = xcol[(size_t)l*512];
        state = s_afw[l]*state + s_bfw[l]*xv;
        cprev = s_C[l];
    }
    state = 0.f; cprev = 0.f;
    for (int lr = 0; lr < L; lr++) {
        int lo = 63 - lr;
        float xv = xcol[(size_t)lo*512];
        s_acc[d][lo] += state * cprev;
        state = s_abw[lo]*state + s_bbw[lo]*xv;
        cprev = s_C[lo];
    }
    for (int l = 0; l < L; l++) {
        int row = (b<<6) + l;
        float xv = xcol[(size_t)l*512];
        float v  = s_acc[d][l] + xv * g_dcoef[row*8 + h];
        float z  = g_zx[(size_t)row*DINPROJ + h*64 + d];
        v *= silu_f(z);
        g_y[(size_t)row*512 + h*64 + d] = v;
    }
}

// RMS norm * norm_w, in-place on g_y
__global__ void k_norm(const float* __restrict__ norm_w) {
    int row = blockIdx.x;
    float* yr = g_y + (size_t)row*512;
    int tid = threadIdx.x;                 // 256
    float v0 = yr[tid], v1 = yr[tid + 256];
    float s = v0*v0 + v1*v1;
    __shared__ float red[8];
#pragma unroll
    for (int o = 16; o > 0; o >>= 1) s += __shfl_down_sync(0xffffffffu, s, o);
    if ((tid & 31) == 0) red[tid >> 5] = s;
    __syncthreads();
    if (tid < 32) {
        float t = (tid < 8) ? red[tid] : 0.f;
#pragma unroll
        for (int o = 4; o > 0; o >>= 1) t += __shfl_down_sync(0xffffffffu, t, o);
        if (tid == 0) red[0] = t;
    }
    __syncthreads();
    float scale = rsqrtf(red[0] * (1.f/512.f) + 1e-5f);
    yr[tid]       = v0 * scale * norm_w[tid];
    yr[tid + 256] = v1 * scale * norm_w[tid + 256];
}

// M2T[b, d, h*64+g] = sum_c outp[b,h,g,c]*to_out_w[d, h*64+c]
// epilogue stores tf32-rounded fp32 K-major
__global__ void k_gemm_m2(const float* __restrict__ to_out_w) {
    int z = blockIdx.z; int b = z >> 3, h = z & 7;
    const float* A  = g_outp + (size_t)z * 4096;                 // 64x64 (g,c)
    const float* Bm = to_out_w + h*64;                           // rows d, ldb 512
    __shared__ float As[16][68];
    __shared__ float Bs[16][68];
    int tid = threadIdx.x;
    int n0 = blockIdx.x * 64;    // over d
    int r = tid >> 2, c4 = (tid & 3) * 4;
    int ty = tid >> 4, tx = tid & 15;
    float acc[4][4] = {};
    for (int kt = 0; kt < 64; kt += 16) {
        float4 av = *(const float4*)(A + (size_t)r*64 + kt + c4);
        As[c4+0][r]=av.x; As[c4+1][r]=av.y; As[c4+2][r]=av.z; As[c4+3][r]=av.w;
        float4 bv = *(const float4*)(Bm + (size_t)(n0 + r)*512 + kt + c4);
        Bs[c4+0][r]=bv.x; Bs[c4+1][r]=bv.y; Bs[c4+2][r]=bv.z; Bs[c4+3][r]=bv.w;
        __syncthreads();
#pragma unroll
        for (int kk = 0; kk < 16; kk++) {
            float a[4], bb[4];
#pragma unroll
            for (int i = 0; i < 4; i++) a[i] = As[kk][ty*4 + i];
#pragma unroll
            for (int j = 0; j < 4; j++) bb[j] = Bs[kk][tx*4 + j];
#pragma unroll
            for (int i = 0; i < 4; i++)
#pragma unroll
                for (int j = 0; j < 4; j++) acc[i][j] += a[i]*bb[j];
        }
        __syncthreads();
    }
#pragma unroll
    for (int i = 0; i < 4; i++)
#pragma unroll
        for (int j = 0; j < 4; j++) {
            size_t o = (size_t)b*262144
                     + (size_t)(n0 + tx*4 + j)*512 + (h*64 + ty*4 + i);
            g_m2t[o] = tf32_rna(acc[i][j]);
        }
}

// ================= TF32 MMA big GEMM =================
// final[b,n,d] = sum_k sw[b,n,k]*M2T[b,d,k] + bias[d]
// Tile 128(n) x 128(d), BK=32, 8 warps (warp tile 64x32), cp.async 2-stage
// (2 stages -> 73.7KB smem -> 3 CTAs/SM; this occupancy is the latency lever).
#define STG_A_BYTES 18432          // 128 rows * 144 B
#define STG_BYTES   36864          // A + B
__global__ void __launch_bounds__(256)
k_gemm_final_mma(const float* __restrict__ swp,
                 const float* __restrict__ bias, float* __restrict__ out) {
    extern __shared__ __align__(16) char dsm[];
    uint32_t sbase = smem_u32(dsm);

    int tid = threadIdx.x;
    int lane = tid & 31, warp = tid >> 5;
    int wm = warp >> 2, wn = warp & 3;          // 2 x 4 warp grid
    int b  = blockIdx.z;
    int d0 = blockIdx.x * 128;
    int n0 = blockIdx.y * 128;

    const size_t swoff = (size_t)b * HEADS * NSEQ * 64;
    const size_t m2off = (size_t)b * 262144;

    float acc[4][4][4] = {};    // [mt][nt][frag]

#define ISSUE_LOADS(it, buf) do {                                           \
    int kt_ = (it) * 32;                                                    \
    int h_  = kt_ >> 6, k64_ = kt_ & 63;                                    \
    uint32_t base_ = sbase + (buf) * STG_BYTES;                             \
    _Pragma("unroll")                                                       \
    for (int i_ = 0; i_ < 4; i_++) {                                        \
        int id_  = tid + 256 * i_;            /* 0..1023 */                 \
        int row_ = id_ >> 3, c_ = id_ & 7;                                  \
        uint32_t doff_ = (uint32_t)(row_ * 144 + c_ * 16);                  \
        int n_ = n0 + row_;                                                 \
        int nc_ = (n_ < NSEQ) ? n_ : (NSEQ - 1);                            \
        uint32_t sz_ = (n_ < NSEQ) ? 16u : 0u;                              \
        size_t aoff_ = swoff + (((size_t)h_*NSEQ + nc_)*64 + k64_ + c_*4);  \
        cp_async16(base_ + doff_, swp + aoff_, sz_);                        \
        int d_ = d0 + row_;                                                 \
        size_t boff_ = m2off + ((size_t)d_*512 + kt_ + c_*4);               \
        cp_async16(base_ + STG_A_BYTES + doff_, g_m2t + boff_, 16u);        \
    }                                                                       \
    CP_COMMIT();                                                            \
} while (0)

    int r4  = lane >> 2;
    int c4l = lane & 3;

    ISSUE_LOADS(0, 0);
    for (int it = 0; it < 16; it++) {
        int buf = it & 1;
        if (it + 1 < 16) {
            ISSUE_LOADS(it + 1, buf ^ 1);
            asm volatile("cp.async.wait_group 1;" ::: "memory");
        } else {
            asm volatile("cp.async.wait_group 0;" ::: "memory");
        }
        __syncthreads();

        const float* As = (const float*)(dsm + buf * STG_BYTES);
        const float* Bs = (const float*)(dsm + buf * STG_BYTES + STG_A_BYTES);

#pragma unroll
        for (int ks = 0; ks < 4; ks++) {
            int col = ks * 8 + c4l;
            uint32_t af[4][4];
#pragma unroll
            for (int mt = 0; mt < 4; mt++) {
                int row = wm*64 + mt*16 + r4;
                af[mt][0] = __float_as_uint(As[row*36 + col]);
                af[mt][1] = __float_as_uint(As[(row+8)*36 + col]);
                af[mt][2] = __float_as_uint(As[row*36 + col + 4]);
                af[mt][3] = __float_as_uint(As[(row+8)*36 + col + 4]);
            }
            uint32_t bf[4][2];
#pragma unroll
            for (int nt = 0; nt < 4; nt++) {
                int n = wn*32 + nt*8 + r4;
                bf[nt][0] = __float_as_uint(Bs[n*36 + col]);
                bf[nt][1] = __float_as_uint(Bs[n*36 + col + 4]);
            }
#pragma unroll
            for (int mt = 0; mt < 4; mt++)
#pragma unroll
                for (int nt = 0; nt < 4; nt++)
                    mma_tf32(acc[mt][nt], af[mt], bf[nt]);
        }
        __syncthreads();
    }
#undef ISSUE_LOADS

    // ---- epilogue ----
#pragma unroll
    for (int mt = 0; mt < 4; mt++) {
        int rbase = n0 + wm*64 + mt*16 + r4;
#pragma unroll
        for (int half = 0; half < 2; half++) {
            int n = rbase + half*8;
            if (n < NSEQ) {
                float* orow = out + ((size_t)b*NSEQ + n)*512;
#pragma unroll
                for (int nt = 0; nt < 4; nt++) {
                    int dcol = d0 + wn*32 + nt*8 + 2*c4l;
                    float2 v;
                    v.x = acc[mt][nt][half*2+0] + bias[dcol];
                    v.y = acc[mt][nt][half*2+1] + bias[dcol+1];
                    *(float2*)(orow + dcol) = v;
                }
            }
        }
    }
}

// ---------------- launch ----------------
extern "C" void kernel_launch(void* const* d_in, const int* in_sizes, int n_in,
                              void* d_out, int out_size) {
    const float* st       = (const float*)d_in[0];   // slice_token
    const float* sw       = (const float*)d_in[1];   // slice_weights
    const float* w_in     = (const float*)d_in[2];
    const float* conv_w   = (const float*)d_in[3];
    const float* conv_b   = (const float*)d_in[4];
    const float* dt_bias  = (const float*)d_in[5];
    const float* A_log    = (const float*)d_in[6];
    const float* Dp       = (const float*)d_in[7];
    const float* fcD      = (const float*)d_in[8];
    const float* norm_w   = (const float*)d_in[9];
    const float* w_out    = (const float*)d_in[10];
    const float* to_out_w = (const float*)d_in[11];
    const float* to_out_b = (const float*)d_in[12];

    float* out      = (float*)d_out;
    float* inp_seg  = out + (size_t)FINAL_ELEMS;
    float* outp_seg = out + (size_t)FINAL_ELEMS + INP_ELEMS;

    const int DSMEM = 2 * STG_BYTES;   // 73728 B -> 3 CTAs/SM
    cudaFuncSetAttribute(k_gemm_final_mma,
                         cudaFuncAttributeMaxDynamicSharedMemorySize, DSMEM);

    // 1. in-projection with fused slice_token gather (1024 x 1042, K=512)
    k_gemm_inproj<<<dim3((DINPROJ + 63)/64, ROWS/64), 256>>>(st, w_in);
    // 2. fused dt + conv + silu + split
    k_conv<<<(ROWS*CONVDIM + 255)/256, 256>>>(conv_w, conv_b, dt_bias);
    // 3. dcoef
    k_dcoef<<<ROWS, 256>>>(fcD, Dp);
    // 4. bidirectional scan (+ D-term + silu(z) gate)
    k_scan<<<dim3(HEADS, B_), 64>>>(A_log);
    // 5. RMS norm
    k_norm<<<ROWS, 256>>>(norm_w);
    // 6. w_out GEMM with fused outp epilogue (writes g_outp + segment 3)
    k_gemm_wout<<<dim3(DM/64, ROWS/64), 256>>>(w_out, outp_seg);
    // 7. inp passthrough (segment 2)
    cudaMemcpyAsync(inp_seg, st, (size_t)INP_ELEMS * sizeof(float),
                    cudaMemcpyDeviceToDevice);
    // 8. M2T = per-(b,h) outp @ to_out_w_block^T -> tf32-rounded K-major
    k_gemm_m2<<<dim3(8, 1, B_*HEADS), 256>>>(to_out_w);
    // 9. final = SW @ M2 + bias via tf32 mma (16 x 3131x512x512), 2-stage
    k_gemm_final_mma<<<dim3(DM/128, (NSEQ + 127)/128, B_), 256, DSMEM>>>(
        sw, to_out_b, out);
}